// round 9
// baseline (speedup 1.0000x reference)
#include <cuda_runtime.h>
#include <cuda_fp16.h>
#include <math.h>
#include <stdint.h>

// ---------------------------------------------------------------------------
// GWNet2: B=64, N=1024, L=13, RC=DC=32, SC=256, EC=512, OUT=12, LAYERS=8
// h layout: [B][L][C][N] fp32. m: same layout, fp16. x12/e1: fp32.
// GEMMs: mma.sync m16n8k16 f16 inputs, f32 accumulate. B operands k-packed
// as half2(B[2i][n], B[2i+1][n]) so fragments load with one LDS.32.
// ---------------------------------------------------------------------------

__device__ float  g_hA  [64 * 13 * 32 * 1024];
__device__ float  g_hB  [64 * 12 * 32 * 1024];
__device__ __half g_m   [64 * 12 * 32 * 1024];       // fp16 A operand
__device__ float  g_x12 [64 * 12 * 32 * 2048];       // (x1 | x2) fp32
__device__ float  g_adpf[1024 * 1024];               // ADP fp32 (for ADP^2)
__device__ __half g_Bm  [2048 * 2048];               // k-packed [ADP | ADP^2]
__device__ __half g_msk [256 * 65536];               // k-packed concat m_last
__device__ __half g_skip[256 * 65536];               // k-packed relu(skip)
__device__ float  g_e1  [512 * 65536];               // fp32
__device__ __half g_w1r [512 * 256];
__device__ __half g_wsk [256 * 256];
__device__ float  g_bsk [256];

// ---------------------------------------------------------------------------
__device__ __forceinline__ void cp16(void* smem, const void* g) {
    unsigned s = (unsigned)__cvta_generic_to_shared(smem);
    asm volatile("cp.async.cg.shared.global [%0], [%1], 16;\n" :: "r"(s), "l"(g));
}

// ---------------------------------------------------------------------------
// adp = softmax(relu(nv1 @ nv2), axis=1) -> fp32 g_adpf + k-packed half g_Bm
// (columns 0..1023 of the fused B matrix)
// ---------------------------------------------------------------------------
__global__ __launch_bounds__(256) void k_adp(const float* __restrict__ nv1,
                                             const float* __restrict__ nv2,
                                             float* __restrict__ adpf,
                                             __half* __restrict__ Bpk) {
    __shared__ float red[256];
    int v = blockIdx.x, tid = threadIdx.x;
    float n1[10];
#pragma unroll
    for (int k = 0; k < 10; k++) n1[k] = nv1[v * 10 + k];
    float a[4];
#pragma unroll
    for (int j = 0; j < 4; j++) {
        int w = tid + j * 256;
        float s = 0.f;
#pragma unroll
        for (int k = 0; k < 10; k++) s += n1[k] * nv2[k * 1024 + w];
        a[j] = fmaxf(s, 0.f);
    }
    float mx = fmaxf(fmaxf(a[0], a[1]), fmaxf(a[2], a[3]));
    red[tid] = mx; __syncthreads();
    for (int s = 128; s > 0; s >>= 1) {
        if (tid < s) red[tid] = fmaxf(red[tid], red[tid + s]);
        __syncthreads();
    }
    mx = red[0]; __syncthreads();
    float e[4]; float sum = 0.f;
#pragma unroll
    for (int j = 0; j < 4; j++) { e[j] = expf(a[j] - mx); sum += e[j]; }
    red[tid] = sum; __syncthreads();
    for (int s = 128; s > 0; s >>= 1) {
        if (tid < s) red[tid] += red[tid + s];
        __syncthreads();
    }
    float inv = 1.f / red[0];
#pragma unroll
    for (int j = 0; j < 4; j++) {
        int w = tid + j * 256;
        float val = e[j] * inv;
        adpf[(long)v * 1024 + w] = val;
        Bpk[((long)(v >> 1) * 2048 + w) * 2 + (v & 1)] = __float2half(val);
    }
}

// ---------------------------------------------------------------------------
__global__ __launch_bounds__(256) void k_start(const float* __restrict__ x,
                                               const float* __restrict__ sw,
                                               const float* __restrict__ sb,
                                               float* __restrict__ h) {
    int bl = blockIdx.x;
    int b = bl / 13, l = bl - b * 13;
    int n = blockIdx.y * 256 + threadIdx.x;
    float x0 = x[(((long)b * 2 + 0) * 1024 + n) * 13 + l];
    float x1 = x[(((long)b * 2 + 1) * 1024 + n) * 13 + l];
    float* hb = h + ((long)(b * 13 + l) * 32) * 1024 + n;
#pragma unroll
    for (int c = 0; c < 32; c++)
        hb[(long)c * 1024] = sw[c * 2] * x0 + sw[c * 2 + 1] * x1 + sb[c];
}

// ---------------------------------------------------------------------------
// dilated conv + tanh*sigmoid; m out fp16; last timestep also k-packed to msk
// ---------------------------------------------------------------------------
__global__ __launch_bounds__(256) void k_dconv(const float* __restrict__ h,
                                               const float* __restrict__ fw,
                                               const float* __restrict__ fb,
                                               const float* __restrict__ gw,
                                               const float* __restrict__ gb,
                                               __half* __restrict__ m,
                                               __half* __restrict__ msk,
                                               int L0, int L1, int d, int layer) {
    __shared__ float s_in[2][32][64];
    __shared__ float4 s_w[32][32];
    __shared__ float s_fb[32], s_gb[32];
    int bl = blockIdx.x;
    int b = bl / L1, l = bl - b * L1;
    int n0 = blockIdx.y * 64;
    int tid = threadIdx.x;
    for (int idx = tid; idx < 1024; idx += 256) {
        int co = idx >> 5, ci = idx & 31;
        int o = (co * 32 + ci) * 2;
        s_w[co][ci] = make_float4(fw[o], fw[o + 1], gw[o], gw[o + 1]);
    }
    if (tid < 32) { s_fb[tid] = fb[tid]; s_gb[tid] = gb[tid]; }
    const float* hb = h + ((long)(b * L0 + l) * 32) * 1024 + n0;
    for (int idx = tid; idx < 4096; idx += 256) {
        int tap = idx >> 11, ci = (idx >> 6) & 31, nl = idx & 63;
        s_in[tap][ci][nl] = hb[((long)(tap * d) * 32 + ci) * 1024 + nl];
    }
    __syncthreads();
    int nl = tid & 63, cg = tid >> 6;
    float fa[8], ga[8];
#pragma unroll
    for (int u = 0; u < 8; u++) { fa[u] = s_fb[cg * 8 + u]; ga[u] = s_gb[cg * 8 + u]; }
#pragma unroll
    for (int ci = 0; ci < 32; ci++) {
        float v0 = s_in[0][ci][nl], v1 = s_in[1][ci][nl];
#pragma unroll
        for (int u = 0; u < 8; u++) {
            float4 w = s_w[cg * 8 + u][ci];
            fa[u] += w.x * v0 + w.y * v1;
            ga[u] += w.z * v0 + w.w * v1;
        }
    }
    __half* mo = m + ((long)(b * L1 + l) * 32) * 1024 + n0 + nl;
    bool last = (l == L1 - 1);
    long col = (long)b * 1024 + n0 + nl;
#pragma unroll
    for (int u = 0; u < 8; u++) {
        int co = cg * 8 + u;
        __half v = __float2half(tanhf(fa[u]) * (1.f / (1.f + expf(-ga[u]))));
        mo[(long)co * 1024] = v;
        if (last) {
            int k = layer * 32 + co;
            msk[((long)(k >> 1) * 65536 + col) * 2 + (k & 1)] = v;
        }
    }
}

// ---------------------------------------------------------------------------
// fp32 SIMT SGEMM: ADP^2 = ADP @ ADP; stores k-packed half into Bpk at
// COLUMNS 1024..2047 (same k rows as ADP — fused [ADP | ADP^2] B matrix).
// ---------------------------------------------------------------------------
__global__ __launch_bounds__(256) void k_sgemm(const float* __restrict__ A,
                                               const float* __restrict__ B,
                                               __half* __restrict__ Bpk) {
    __shared__ float As[16][132];
    __shared__ float Bs[16][128];
    int tid = threadIdx.x;
    int m0 = blockIdx.y * 128, n0 = blockIdx.x * 128;
    int ty = tid >> 4, tx = tid & 15;
    float acc[8][8];
#pragma unroll
    for (int i = 0; i < 8; i++)
#pragma unroll
        for (int j = 0; j < 8; j++) acc[i][j] = 0.f;

    for (int k0 = 0; k0 < 1024; k0 += 16) {
#pragma unroll
        for (int i = 0; i < 2; i++) {
            int f = tid + i * 256;
            int r = f >> 2, kc = (f & 3) * 4;
            float4 v = *(const float4*)(A + (long)(m0 + r) * 1024 + k0 + kc);
            As[kc + 0][r] = v.x; As[kc + 1][r] = v.y;
            As[kc + 2][r] = v.z; As[kc + 3][r] = v.w;
        }
#pragma unroll
        for (int i = 0; i < 2; i++) {
            int f = tid + i * 256;
            int r = f >> 5, nc = (f & 31) * 4;
            float4 v = *(const float4*)(B + (long)(k0 + r) * 1024 + n0 + nc);
            *(float4*)&Bs[r][nc] = v;
        }
        __syncthreads();
#pragma unroll
        for (int k = 0; k < 16; k++) {
            float a[8], b[8];
            float4 a0 = *(const float4*)&As[k][ty * 8];
            float4 a1 = *(const float4*)&As[k][ty * 8 + 4];
            a[0] = a0.x; a[1] = a0.y; a[2] = a0.z; a[3] = a0.w;
            a[4] = a1.x; a[5] = a1.y; a[6] = a1.z; a[7] = a1.w;
            float4 b0 = *(const float4*)&Bs[k][tx * 8];
            float4 b1 = *(const float4*)&Bs[k][tx * 8 + 4];
            b[0] = b0.x; b[1] = b0.y; b[2] = b0.z; b[3] = b0.w;
            b[4] = b1.x; b[5] = b1.y; b[6] = b1.z; b[7] = b1.w;
#pragma unroll
            for (int i = 0; i < 8; i++)
#pragma unroll
                for (int j = 0; j < 8; j++) acc[i][j] += a[i] * b[j];
        }
        __syncthreads();
    }
#pragma unroll
    for (int i = 0; i < 8; i++) {
        int v = m0 + ty * 8 + i;   // k row index
#pragma unroll
        for (int j = 0; j < 8; j++) {
            int w = n0 + tx * 8 + j;
            Bpk[((long)(v >> 1) * 2048 + 1024 + w) * 2 + (v & 1)] =
                __float2half(acc[i][j]);
        }
    }
}

// ---------------------------------------------------------------------------
// fp16 tensor-core GEMM (m16n8k16, f32 acc), cp.async double-buffered.
// C[M,N] = A[M,K] @ B[K,N]. A: half, row-major (lda halves). B: k-packed half2
// (ldb2 = N stride in half2). CTA 128x256, 8 warps, warp tile 64x64.
// flags bit1: +bias[row], relu. bit2: C stored k-packed half (else fp32).
// M mult 128, N mult 256, K mult 32.
// ---------------------------------------------------------------------------
__global__ __launch_bounds__(256) void k_gemm_f16(const __half* __restrict__ A,
                                                  const half2* __restrict__ Bpk,
                                                  void* __restrict__ Cv,
                                                  int K, int lda, long ldb2, long ldc,
                                                  const float* __restrict__ bias,
                                                  int flags) {
    __shared__ __half As[2][128][40];    // [m][k halves], pad 40 (20 words)
    __shared__ half2  Bs[2][16][264];    // [k/2][n], pad 264
    int tid = threadIdx.x;
    int m0 = blockIdx.y * 128;
    long n0 = (long)blockIdx.x * 256;
    int w = tid >> 5, lane = tid & 31;
    int grp = lane >> 2, tg = lane & 3;
    int wm = (w & 1) * 64, wn = (w >> 1) * 64;

    float acc[4][8][4];
#pragma unroll
    for (int mt = 0; mt < 4; mt++)
#pragma unroll
        for (int nt = 0; nt < 8; nt++)
#pragma unroll
            for (int c = 0; c < 4; c++) acc[mt][nt][c] = 0.f;

    int nstage = K / 32;
    {
#pragma unroll
        for (int i = 0; i < 2; i++) {
            int ch = tid + i * 256;
            int r = ch >> 2, p = (ch & 3) * 8;
            cp16(&As[0][r][p], A + (long)(m0 + r) * lda + p);
        }
#pragma unroll
        for (int i = 0; i < 4; i++) {
            int ch = tid + i * 256;
            int r = ch >> 6, c4 = (ch & 63) * 4;
            cp16(&Bs[0][r][c4], Bpk + (long)r * ldb2 + n0 + c4);
        }
        asm volatile("cp.async.commit_group;\n");
    }

    for (int s = 0; s < nstage; s++) {
        int buf = s & 1;
        if (s + 1 < nstage) {
            int nb = buf ^ 1;
            int k0 = (s + 1) * 32;
#pragma unroll
            for (int i = 0; i < 2; i++) {
                int ch = tid + i * 256;
                int r = ch >> 2, p = (ch & 3) * 8;
                cp16(&As[nb][r][p], A + (long)(m0 + r) * lda + k0 + p);
            }
#pragma unroll
            for (int i = 0; i < 4; i++) {
                int ch = tid + i * 256;
                int r = ch >> 6, c4 = (ch & 63) * 4;
                cp16(&Bs[nb][r][c4], Bpk + (long)(k0 / 2 + r) * ldb2 + n0 + c4);
            }
            asm volatile("cp.async.commit_group;\n");
            asm volatile("cp.async.wait_group 1;\n");
        } else {
            asm volatile("cp.async.wait_group 0;\n");
        }
        __syncthreads();

#pragma unroll
        for (int s2 = 0; s2 < 2; s2++) {
            unsigned a[4][4];
#pragma unroll
            for (int mt = 0; mt < 4; mt++) {
                int rb = wm + mt * 16;
                a[mt][0] = *(const unsigned*)&As[buf][rb + grp][s2 * 16 + tg * 2];
                a[mt][1] = *(const unsigned*)&As[buf][rb + grp + 8][s2 * 16 + tg * 2];
                a[mt][2] = *(const unsigned*)&As[buf][rb + grp][s2 * 16 + tg * 2 + 8];
                a[mt][3] = *(const unsigned*)&As[buf][rb + grp + 8][s2 * 16 + tg * 2 + 8];
            }
            unsigned b[8][2];
#pragma unroll
            for (int nt = 0; nt < 8; nt++) {
                int cb = wn + nt * 8 + grp;
                b[nt][0] = *(const unsigned*)&Bs[buf][s2 * 8 + tg][cb];
                b[nt][1] = *(const unsigned*)&Bs[buf][s2 * 8 + tg + 4][cb];
            }
#pragma unroll
            for (int mt = 0; mt < 4; mt++)
#pragma unroll
                for (int nt = 0; nt < 8; nt++) {
                    asm volatile(
                        "mma.sync.aligned.m16n8k16.row.col.f32.f16.f16.f32 "
                        "{%0,%1,%2,%3}, {%4,%5,%6,%7}, {%8,%9}, {%0,%1,%2,%3};\n"
                        : "+f"(acc[mt][nt][0]), "+f"(acc[mt][nt][1]),
                          "+f"(acc[mt][nt][2]), "+f"(acc[mt][nt][3])
                        : "r"(a[mt][0]), "r"(a[mt][1]), "r"(a[mt][2]), "r"(a[mt][3]),
                          "r"(b[nt][0]), "r"(b[nt][1]));
                }
        }
        __syncthreads();
    }

    float* Cf = (float*)Cv;
    __half* Ch = (__half*)Cv;
#pragma unroll
    for (int mt = 0; mt < 4; mt++) {
        int row0 = m0 + wm + mt * 16 + grp;
        int row1 = row0 + 8;
        float b0 = 0.f, b1 = 0.f;
        if (flags & 2) { b0 = bias[row0]; b1 = bias[row1]; }
#pragma unroll
        for (int nt = 0; nt < 8; nt++) {
            long col = n0 + wn + nt * 8 + tg * 2;
            float v00 = acc[mt][nt][0], v01 = acc[mt][nt][1];
            float v10 = acc[mt][nt][2], v11 = acc[mt][nt][3];
            if (flags & 2) {
                v00 = fmaxf(v00 + b0, 0.f); v01 = fmaxf(v01 + b0, 0.f);
                v10 = fmaxf(v10 + b1, 0.f); v11 = fmaxf(v11 + b1, 0.f);
            }
            if (flags & 4) {
                long p0 = ((long)(row0 >> 1) * ldc + col) * 2 + (row0 & 1);
                long p1 = ((long)(row1 >> 1) * ldc + col) * 2 + (row1 & 1);
                Ch[p0] = __float2half(v00); Ch[p0 + 2] = __float2half(v01);
                Ch[p1] = __float2half(v10); Ch[p1 + 2] = __float2half(v11);
            } else {
                *(float2*)(Cf + (long)row0 * ldc + col) = make_float2(v00, v01);
                *(float2*)(Cf + (long)row1 * ldc + col) = make_float2(v10, v11);
            }
        }
    }
}

// ---------------------------------------------------------------------------
// gc mix + residual + BN (m read as fp16)
// ---------------------------------------------------------------------------
__global__ __launch_bounds__(256) void k_gc(const __half* __restrict__ m,
                                            const float* __restrict__ x12,
                                            const float* __restrict__ hold,
                                            const float* __restrict__ gcw,
                                            const float* __restrict__ gcb,
                                            const float* __restrict__ bng,
                                            const float* __restrict__ bnb,
                                            float* __restrict__ hnew,
                                            int L0, int L1, int d) {
    __shared__ float s_in[3][32][64];
    __shared__ float4 s_w[32][32];
    __shared__ float s_b[32], s_sc[32], s_sh[32];
    int bl = blockIdx.x;
    int b = bl / L1, l = bl - b * L1;
    int n0 = blockIdx.y * 64;
    int tid = threadIdx.x;
    for (int idx = tid; idx < 1024; idx += 256) {
        int co = idx >> 5, ci = idx & 31;
        s_w[co][ci] = make_float4(gcw[co * 96 + ci], gcw[co * 96 + 32 + ci],
                                  gcw[co * 96 + 64 + ci], 0.f);
    }
    if (tid < 32) {
        s_b[tid] = gcb[tid];
        s_sc[tid] = bng[tid] * rsqrtf(1.f + 1e-5f);
        s_sh[tid] = bnb[tid];
    }
    const __half* mb = m + ((long)(b * L1 + l) * 32) * 1024 + n0;
    const float* xb = x12 + ((long)(b * L1 + l) * 32) * 2048 + n0;
    for (int idx = tid; idx < 2048; idx += 256) {
        int ci = idx >> 6, nl = idx & 63;
        s_in[0][ci][nl] = __half2float(mb[(long)ci * 1024 + nl]);
        s_in[1][ci][nl] = xb[(long)ci * 2048 + nl];
        s_in[2][ci][nl] = xb[(long)ci * 2048 + 1024 + nl];
    }
    __syncthreads();
    int nl = tid & 63, cg = tid >> 6;
    float acc[8];
#pragma unroll
    for (int u = 0; u < 8; u++) acc[u] = s_b[cg * 8 + u];
#pragma unroll
    for (int ci = 0; ci < 32; ci++) {
        float v0 = s_in[0][ci][nl], v1 = s_in[1][ci][nl], v2 = s_in[2][ci][nl];
#pragma unroll
        for (int u = 0; u < 8; u++) {
            float4 w = s_w[cg * 8 + u][ci];
            acc[u] += w.x * v0 + w.y * v1 + w.z * v2;
        }
    }
    const float* rb = hold + ((long)(b * L0 + l + d) * 32) * 1024 + n0 + nl;
    float* ob = hnew + ((long)(b * L1 + l) * 32) * 1024 + n0 + nl;
#pragma unroll
    for (int u = 0; u < 8; u++) {
        int co = cg * 8 + u;
        float res = rb[(long)co * 1024];
        ob[(long)co * 1024] = (acc[u] + res) * s_sc[co] + s_sh[co];
    }
}

// ---------------------------------------------------------------------------
// prep: concat skip weights (half) + summed skip bias; round end1_w to half
// ---------------------------------------------------------------------------
__global__ __launch_bounds__(256) void k_prep(const float* __restrict__ skw,
                                              const float* __restrict__ skb,
                                              __half* __restrict__ wcat,
                                              float* __restrict__ bsum) {
    int co = blockIdx.x, k = threadIdx.x;
    int i = k >> 5, ci = k & 31;
    wcat[co * 256 + k] = __float2half(skw[((long)i * 256 + co) * 32 + ci]);
    if (k == 0) {
        float s = 0.f;
#pragma unroll
        for (int j = 0; j < 8; j++) s += skb[j * 256 + co];
        bsum[co] = s;
    }
}
__global__ __launch_bounds__(256) void k_roundh(const float* __restrict__ w,
                                                __half* __restrict__ o) {
    int i = blockIdx.x * 256 + threadIdx.x;
    o[i] = __float2half(w[i]);
}

// ---------------------------------------------------------------------------
__global__ __launch_bounds__(256) void k_end2(const float* __restrict__ e1,
                                              const float* __restrict__ w2,
                                              const float* __restrict__ b2,
                                              float* __restrict__ out) {
    __shared__ float s_w[12 * 512];
    int tid = threadIdx.x;
    for (int idx = tid; idx < 6144; idx += 256) s_w[idx] = w2[idx];
    __syncthreads();
    int col = blockIdx.x * 256 + tid;
    int b = col >> 10, n = col & 1023;
    float acc[12];
#pragma unroll
    for (int o = 0; o < 12; o++) acc[o] = b2[o];
    for (int c = 0; c < 512; c++) {
        float v = e1[(long)c * 65536 + col];
#pragma unroll
        for (int o = 0; o < 12; o++) acc[o] += s_w[o * 512 + c] * v;
    }
#pragma unroll
    for (int o = 0; o < 12; o++) out[((long)b * 12 + o) * 1024 + n] = acc[o];
}

// ---------------------------------------------------------------------------
extern "C" void kernel_launch(void* const* d_in, const int* in_sizes, int n_in,
                              void* d_out, int out_size) {
    const float* x        = (const float*)d_in[0];
    const float* start_w  = (const float*)d_in[1];
    const float* start_b  = (const float*)d_in[2];
    const float* nodevec1 = (const float*)d_in[3];
    const float* nodevec2 = (const float*)d_in[4];
    const float* filter_w = (const float*)d_in[5];
    const float* filter_b = (const float*)d_in[6];
    const float* gate_w   = (const float*)d_in[7];
    const float* gate_b   = (const float*)d_in[8];
    const float* skip_w   = (const float*)d_in[9];
    const float* skip_b   = (const float*)d_in[10];
    const float* gc_w     = (const float*)d_in[11];
    const float* gc_b     = (const float*)d_in[12];
    const float* bn_g     = (const float*)d_in[13];
    const float* bn_b     = (const float*)d_in[14];
    const float* end1_w   = (const float*)d_in[15];
    const float* end1_b   = (const float*)d_in[16];
    const float* end2_w   = (const float*)d_in[17];
    const float* end2_b   = (const float*)d_in[18];

    float *hA, *hB, *x12, *adpf, *e1, *bsk;
    __half *m, *Bm, *msk, *skip, *w1r, *wsk;
    cudaGetSymbolAddress((void**)&hA, g_hA);
    cudaGetSymbolAddress((void**)&hB, g_hB);
    cudaGetSymbolAddress((void**)&m, g_m);
    cudaGetSymbolAddress((void**)&x12, g_x12);
    cudaGetSymbolAddress((void**)&adpf, g_adpf);
    cudaGetSymbolAddress((void**)&Bm, g_Bm);
    cudaGetSymbolAddress((void**)&msk, g_msk);
    cudaGetSymbolAddress((void**)&skip, g_skip);
    cudaGetSymbolAddress((void**)&e1, g_e1);
    cudaGetSymbolAddress((void**)&w1r, g_w1r);
    cudaGetSymbolAddress((void**)&wsk, g_wsk);
    cudaGetSymbolAddress((void**)&bsk, g_bsk);

    k_adp<<<1024, 256>>>(nodevec1, nodevec2, adpf, Bm);
    k_sgemm<<<dim3(8, 8), 256>>>(adpf, adpf, Bm);
    k_start<<<dim3(64 * 13, 4), 256>>>(x, start_w, start_b, hA);
    k_roundh<<<512, 256>>>(end1_w, w1r);
    k_prep<<<256, 256>>>(skip_w, skip_b, wsk, bsk);

    const int lens[9] = {13, 12, 10, 9, 7, 6, 4, 3, 1};
    const int dil[8]  = {1, 2, 1, 2, 1, 2, 1, 2};
    float* hcur = hA;
    float* hnext = hB;

    for (int i = 0; i < 8; i++) {
        int L0 = lens[i], L1 = lens[i + 1], d = dil[i];
        k_dconv<<<dim3(64 * L1, 16), 256>>>(hcur,
                                            filter_w + i * 2048, filter_b + i * 32,
                                            gate_w + i * 2048, gate_b + i * 32,
                                            m, msk, L0, L1, d, i);
        if (i < 7) {
            int M = 2048 * L1;
            // x12 = m @ [ADP | ADP^2]
            k_gemm_f16<<<dim3(2048 / 256, M / 128), 256>>>(
                m, (const half2*)Bm, x12, 1024, 1024, 2048, 2048, nullptr, 0);
            k_gc<<<dim3(64 * L1, 16), 256>>>(m, x12, hcur,
                                             gc_w + i * 32 * 96, gc_b + i * 32,
                                             bn_g + i * 32, bn_b + i * 32,
                                             hnext, L0, L1, d);
            float* t = hcur; hcur = hnext; hnext = t;
        }
    }

    // skip = relu(Wcat @ msk + bsum), stored k-packed half
    k_gemm_f16<<<dim3(65536 / 256, 2), 256>>>(
        wsk, (const half2*)msk, skip, 256, 256, 65536, 65536, bsk, 2 | 4);
    // e1 = relu(W1 @ skip + b1), fp32
    k_gemm_f16<<<dim3(65536 / 256, 4), 256>>>(
        w1r, (const half2*)skip, e1, 256, 256, 65536, 65536, end1_b, 2);
    k_end2<<<256, 256>>>(e1, end2_w, end2_b, (float*)d_out);
}

// round 10
// speedup vs baseline: 1.0001x; 1.0001x over previous
#include <cuda_runtime.h>
#include <cuda_fp16.h>
#include <math.h>
#include <stdint.h>

// ---------------------------------------------------------------------------
// GWNet2: B=64, N=1024, L=13, RC=DC=32, SC=256, EC=512, OUT=12, LAYERS=8
// h layout: [B][L][C][N] fp32. m: same layout, fp16. x12/e1: fp32.
// GEMMs: mma.sync m16n8k16 f16 inputs, f32 accumulate. B operands k-packed
// as half2(B[2i][n], B[2i+1][n]) so fragments load with one LDS.32.
// ---------------------------------------------------------------------------

__device__ float  g_hA  [64 * 13 * 32 * 1024];
__device__ float  g_hB  [64 * 12 * 32 * 1024];
__device__ __half g_m   [64 * 12 * 32 * 1024];       // fp16 A operand
__device__ float  g_x12 [64 * 12 * 32 * 2048];       // (x1 | x2) fp32
__device__ float  g_adpf[1024 * 1024];               // ADP fp32 (for ADP^2)
__device__ __half g_Bm  [2048 * 2048];               // k-packed [ADP | ADP^2]
__device__ __half g_msk [256 * 65536];               // k-packed concat m_last
__device__ __half g_skip[256 * 65536];               // k-packed relu(skip)
__device__ float  g_e1  [512 * 65536];               // fp32
__device__ __half g_w1r [512 * 256];
__device__ __half g_wsk [256 * 256];
__device__ float  g_bsk [256];

// ---------------------------------------------------------------------------
__device__ __forceinline__ void cp16(void* smem, const void* g) {
    unsigned s = (unsigned)__cvta_generic_to_shared(smem);
    asm volatile("cp.async.cg.shared.global [%0], [%1], 16;\n" :: "r"(s), "l"(g));
}

// ---------------------------------------------------------------------------
// adp = softmax(relu(nv1 @ nv2), axis=1) -> fp32 g_adpf + k-packed half g_Bm
// (columns 0..1023 of the fused B matrix)
// ---------------------------------------------------------------------------
__global__ __launch_bounds__(256) void k_adp(const float* __restrict__ nv1,
                                             const float* __restrict__ nv2,
                                             float* __restrict__ adpf,
                                             __half* __restrict__ Bpk) {
    __shared__ float red[256];
    int v = blockIdx.x, tid = threadIdx.x;
    float n1[10];
#pragma unroll
    for (int k = 0; k < 10; k++) n1[k] = nv1[v * 10 + k];
    float a[4];
#pragma unroll
    for (int j = 0; j < 4; j++) {
        int w = tid + j * 256;
        float s = 0.f;
#pragma unroll
        for (int k = 0; k < 10; k++) s += n1[k] * nv2[k * 1024 + w];
        a[j] = fmaxf(s, 0.f);
    }
    float mx = fmaxf(fmaxf(a[0], a[1]), fmaxf(a[2], a[3]));
    red[tid] = mx; __syncthreads();
    for (int s = 128; s > 0; s >>= 1) {
        if (tid < s) red[tid] = fmaxf(red[tid], red[tid + s]);
        __syncthreads();
    }
    mx = red[0]; __syncthreads();
    float e[4]; float sum = 0.f;
#pragma unroll
    for (int j = 0; j < 4; j++) { e[j] = expf(a[j] - mx); sum += e[j]; }
    red[tid] = sum; __syncthreads();
    for (int s = 128; s > 0; s >>= 1) {
        if (tid < s) red[tid] += red[tid + s];
        __syncthreads();
    }
    float inv = 1.f / red[0];
#pragma unroll
    for (int j = 0; j < 4; j++) {
        int w = tid + j * 256;
        float val = e[j] * inv;
        adpf[(long)v * 1024 + w] = val;
        Bpk[((long)(v >> 1) * 2048 + w) * 2 + (v & 1)] = __float2half(val);
    }
}

// ---------------------------------------------------------------------------
__global__ __launch_bounds__(256) void k_start(const float* __restrict__ x,
                                               const float* __restrict__ sw,
                                               const float* __restrict__ sb,
                                               float* __restrict__ h) {
    int bl = blockIdx.x;
    int b = bl / 13, l = bl - b * 13;
    int n = blockIdx.y * 256 + threadIdx.x;
    float x0 = x[(((long)b * 2 + 0) * 1024 + n) * 13 + l];
    float x1 = x[(((long)b * 2 + 1) * 1024 + n) * 13 + l];
    float* hb = h + ((long)(b * 13 + l) * 32) * 1024 + n;
#pragma unroll
    for (int c = 0; c < 32; c++)
        hb[(long)c * 1024] = sw[c * 2] * x0 + sw[c * 2 + 1] * x1 + sb[c];
}

// ---------------------------------------------------------------------------
// dilated conv + tanh*sigmoid; m out fp16; last timestep also k-packed to msk
// ---------------------------------------------------------------------------
__global__ __launch_bounds__(256) void k_dconv(const float* __restrict__ h,
                                               const float* __restrict__ fw,
                                               const float* __restrict__ fb,
                                               const float* __restrict__ gw,
                                               const float* __restrict__ gb,
                                               __half* __restrict__ m,
                                               __half* __restrict__ msk,
                                               int L0, int L1, int d, int layer) {
    __shared__ float s_in[2][32][64];
    __shared__ float4 s_w[32][32];
    __shared__ float s_fb[32], s_gb[32];
    int bl = blockIdx.x;
    int b = bl / L1, l = bl - b * L1;
    int n0 = blockIdx.y * 64;
    int tid = threadIdx.x;
    for (int idx = tid; idx < 1024; idx += 256) {
        int co = idx >> 5, ci = idx & 31;
        int o = (co * 32 + ci) * 2;
        s_w[co][ci] = make_float4(fw[o], fw[o + 1], gw[o], gw[o + 1]);
    }
    if (tid < 32) { s_fb[tid] = fb[tid]; s_gb[tid] = gb[tid]; }
    const float* hb = h + ((long)(b * L0 + l) * 32) * 1024 + n0;
    for (int idx = tid; idx < 4096; idx += 256) {
        int tap = idx >> 11, ci = (idx >> 6) & 31, nl = idx & 63;
        s_in[tap][ci][nl] = hb[((long)(tap * d) * 32 + ci) * 1024 + nl];
    }
    __syncthreads();
    int nl = tid & 63, cg = tid >> 6;
    float fa[8], ga[8];
#pragma unroll
    for (int u = 0; u < 8; u++) { fa[u] = s_fb[cg * 8 + u]; ga[u] = s_gb[cg * 8 + u]; }
#pragma unroll
    for (int ci = 0; ci < 32; ci++) {
        float v0 = s_in[0][ci][nl], v1 = s_in[1][ci][nl];
#pragma unroll
        for (int u = 0; u < 8; u++) {
            float4 w = s_w[cg * 8 + u][ci];
            fa[u] += w.x * v0 + w.y * v1;
            ga[u] += w.z * v0 + w.w * v1;
        }
    }
    __half* mo = m + ((long)(b * L1 + l) * 32) * 1024 + n0 + nl;
    bool last = (l == L1 - 1);
    long col = (long)b * 1024 + n0 + nl;
#pragma unroll
    for (int u = 0; u < 8; u++) {
        int co = cg * 8 + u;
        __half v = __float2half(tanhf(fa[u]) * (1.f / (1.f + expf(-ga[u]))));
        mo[(long)co * 1024] = v;
        if (last) {
            int k = layer * 32 + co;
            msk[((long)(k >> 1) * 65536 + col) * 2 + (k & 1)] = v;
        }
    }
}

// ---------------------------------------------------------------------------
// fp32 SIMT SGEMM: ADP^2 = ADP @ ADP; stores k-packed half into Bpk at
// COLUMNS 1024..2047 (same k rows as ADP — fused [ADP | ADP^2] B matrix).
// ---------------------------------------------------------------------------
__global__ __launch_bounds__(256) void k_sgemm(const float* __restrict__ A,
                                               const float* __restrict__ B,
                                               __half* __restrict__ Bpk) {
    __shared__ float As[16][132];
    __shared__ float Bs[16][128];
    int tid = threadIdx.x;
    int m0 = blockIdx.y * 128, n0 = blockIdx.x * 128;
    int ty = tid >> 4, tx = tid & 15;
    float acc[8][8];
#pragma unroll
    for (int i = 0; i < 8; i++)
#pragma unroll
        for (int j = 0; j < 8; j++) acc[i][j] = 0.f;

    for (int k0 = 0; k0 < 1024; k0 += 16) {
#pragma unroll
        for (int i = 0; i < 2; i++) {
            int f = tid + i * 256;
            int r = f >> 2, kc = (f & 3) * 4;
            float4 v = *(const float4*)(A + (long)(m0 + r) * 1024 + k0 + kc);
            As[kc + 0][r] = v.x; As[kc + 1][r] = v.y;
            As[kc + 2][r] = v.z; As[kc + 3][r] = v.w;
        }
#pragma unroll
        for (int i = 0; i < 2; i++) {
            int f = tid + i * 256;
            int r = f >> 5, nc = (f & 31) * 4;
            float4 v = *(const float4*)(B + (long)(k0 + r) * 1024 + n0 + nc);
            *(float4*)&Bs[r][nc] = v;
        }
        __syncthreads();
#pragma unroll
        for (int k = 0; k < 16; k++) {
            float a[8], b[8];
            float4 a0 = *(const float4*)&As[k][ty * 8];
            float4 a1 = *(const float4*)&As[k][ty * 8 + 4];
            a[0] = a0.x; a[1] = a0.y; a[2] = a0.z; a[3] = a0.w;
            a[4] = a1.x; a[5] = a1.y; a[6] = a1.z; a[7] = a1.w;
            float4 b0 = *(const float4*)&Bs[k][tx * 8];
            float4 b1 = *(const float4*)&Bs[k][tx * 8 + 4];
            b[0] = b0.x; b[1] = b0.y; b[2] = b0.z; b[3] = b0.w;
            b[4] = b1.x; b[5] = b1.y; b[6] = b1.z; b[7] = b1.w;
#pragma unroll
            for (int i = 0; i < 8; i++)
#pragma unroll
                for (int j = 0; j < 8; j++) acc[i][j] += a[i] * b[j];
        }
        __syncthreads();
    }
#pragma unroll
    for (int i = 0; i < 8; i++) {
        int v = m0 + ty * 8 + i;   // k row index
#pragma unroll
        for (int j = 0; j < 8; j++) {
            int w = n0 + tx * 8 + j;
            Bpk[((long)(v >> 1) * 2048 + 1024 + w) * 2 + (v & 1)] =
                __float2half(acc[i][j]);
        }
    }
}

// ---------------------------------------------------------------------------
// fp16 tensor-core GEMM (m16n8k16, f32 acc), cp.async double-buffered.
// C[M,N] = A[M,K] @ B[K,N]. A: half, row-major (lda halves). B: k-packed half2
// (ldb2 = N stride in half2). CTA 128x256, 8 warps, warp tile 64x64.
// flags bit1: +bias[row], relu. bit2: C stored k-packed half (else fp32).
// M mult 128, N mult 256, K mult 32.
// ---------------------------------------------------------------------------
__global__ __launch_bounds__(256) void k_gemm_f16(const __half* __restrict__ A,
                                                  const half2* __restrict__ Bpk,
                                                  void* __restrict__ Cv,
                                                  int K, int lda, long ldb2, long ldc,
                                                  const float* __restrict__ bias,
                                                  int flags) {
    __shared__ __half As[2][128][40];    // [m][k halves], pad 40 (20 words)
    __shared__ half2  Bs[2][16][264];    // [k/2][n], pad 264
    int tid = threadIdx.x;
    int m0 = blockIdx.y * 128;
    long n0 = (long)blockIdx.x * 256;
    int w = tid >> 5, lane = tid & 31;
    int grp = lane >> 2, tg = lane & 3;
    int wm = (w & 1) * 64, wn = (w >> 1) * 64;

    float acc[4][8][4];
#pragma unroll
    for (int mt = 0; mt < 4; mt++)
#pragma unroll
        for (int nt = 0; nt < 8; nt++)
#pragma unroll
            for (int c = 0; c < 4; c++) acc[mt][nt][c] = 0.f;

    int nstage = K / 32;
    {
#pragma unroll
        for (int i = 0; i < 2; i++) {
            int ch = tid + i * 256;
            int r = ch >> 2, p = (ch & 3) * 8;
            cp16(&As[0][r][p], A + (long)(m0 + r) * lda + p);
        }
#pragma unroll
        for (int i = 0; i < 4; i++) {
            int ch = tid + i * 256;
            int r = ch >> 6, c4 = (ch & 63) * 4;
            cp16(&Bs[0][r][c4], Bpk + (long)r * ldb2 + n0 + c4);
        }
        asm volatile("cp.async.commit_group;\n");
    }

    for (int s = 0; s < nstage; s++) {
        int buf = s & 1;
        if (s + 1 < nstage) {
            int nb = buf ^ 1;
            int k0 = (s + 1) * 32;
#pragma unroll
            for (int i = 0; i < 2; i++) {
                int ch = tid + i * 256;
                int r = ch >> 2, p = (ch & 3) * 8;
                cp16(&As[nb][r][p], A + (long)(m0 + r) * lda + k0 + p);
            }
#pragma unroll
            for (int i = 0; i < 4; i++) {
                int ch = tid + i * 256;
                int r = ch >> 6, c4 = (ch & 63) * 4;
                cp16(&Bs[nb][r][c4], Bpk + (long)(k0 / 2 + r) * ldb2 + n0 + c4);
            }
            asm volatile("cp.async.commit_group;\n");
            asm volatile("cp.async.wait_group 1;\n");
        } else {
            asm volatile("cp.async.wait_group 0;\n");
        }
        __syncthreads();

#pragma unroll
        for (int s2 = 0; s2 < 2; s2++) {
            unsigned a[4][4];
#pragma unroll
            for (int mt = 0; mt < 4; mt++) {
                int rb = wm + mt * 16;
                a[mt][0] = *(const unsigned*)&As[buf][rb + grp][s2 * 16 + tg * 2];
                a[mt][1] = *(const unsigned*)&As[buf][rb + grp + 8][s2 * 16 + tg * 2];
                a[mt][2] = *(const unsigned*)&As[buf][rb + grp][s2 * 16 + tg * 2 + 8];
                a[mt][3] = *(const unsigned*)&As[buf][rb + grp + 8][s2 * 16 + tg * 2 + 8];
            }
            unsigned b[8][2];
#pragma unroll
            for (int nt = 0; nt < 8; nt++) {
                int cb = wn + nt * 8 + grp;
                b[nt][0] = *(const unsigned*)&Bs[buf][s2 * 8 + tg][cb];
                b[nt][1] = *(const unsigned*)&Bs[buf][s2 * 8 + tg + 4][cb];
            }
#pragma unroll
            for (int mt = 0; mt < 4; mt++)
#pragma unroll
                for (int nt = 0; nt < 8; nt++) {
                    asm volatile(
                        "mma.sync.aligned.m16n8k16.row.col.f32.f16.f16.f32 "
                        "{%0,%1,%2,%3}, {%4,%5,%6,%7}, {%8,%9}, {%0,%1,%2,%3};\n"
                        : "+f"(acc[mt][nt][0]), "+f"(acc[mt][nt][1]),
                          "+f"(acc[mt][nt][2]), "+f"(acc[mt][nt][3])
                        : "r"(a[mt][0]), "r"(a[mt][1]), "r"(a[mt][2]), "r"(a[mt][3]),
                          "r"(b[nt][0]), "r"(b[nt][1]));
                }
        }
        __syncthreads();
    }

    float* Cf = (float*)Cv;
    __half* Ch = (__half*)Cv;
#pragma unroll
    for (int mt = 0; mt < 4; mt++) {
        int row0 = m0 + wm + mt * 16 + grp;
        int row1 = row0 + 8;
        float b0 = 0.f, b1 = 0.f;
        if (flags & 2) { b0 = bias[row0]; b1 = bias[row1]; }
#pragma unroll
        for (int nt = 0; nt < 8; nt++) {
            long col = n0 + wn + nt * 8 + tg * 2;
            float v00 = acc[mt][nt][0], v01 = acc[mt][nt][1];
            float v10 = acc[mt][nt][2], v11 = acc[mt][nt][3];
            if (flags & 2) {
                v00 = fmaxf(v00 + b0, 0.f); v01 = fmaxf(v01 + b0, 0.f);
                v10 = fmaxf(v10 + b1, 0.f); v11 = fmaxf(v11 + b1, 0.f);
            }
            if (flags & 4) {
                long p0 = ((long)(row0 >> 1) * ldc + col) * 2 + (row0 & 1);
                long p1 = ((long)(row1 >> 1) * ldc + col) * 2 + (row1 & 1);
                Ch[p0] = __float2half(v00); Ch[p0 + 2] = __float2half(v01);
                Ch[p1] = __float2half(v10); Ch[p1 + 2] = __float2half(v11);
            } else {
                *(float2*)(Cf + (long)row0 * ldc + col) = make_float2(v00, v01);
                *(float2*)(Cf + (long)row1 * ldc + col) = make_float2(v10, v11);
            }
        }
    }
}

// ---------------------------------------------------------------------------
// gc mix + residual + BN (m read as fp16)
// ---------------------------------------------------------------------------
__global__ __launch_bounds__(256) void k_gc(const __half* __restrict__ m,
                                            const float* __restrict__ x12,
                                            const float* __restrict__ hold,
                                            const float* __restrict__ gcw,
                                            const float* __restrict__ gcb,
                                            const float* __restrict__ bng,
                                            const float* __restrict__ bnb,
                                            float* __restrict__ hnew,
                                            int L0, int L1, int d) {
    __shared__ float s_in[3][32][64];
    __shared__ float4 s_w[32][32];
    __shared__ float s_b[32], s_sc[32], s_sh[32];
    int bl = blockIdx.x;
    int b = bl / L1, l = bl - b * L1;
    int n0 = blockIdx.y * 64;
    int tid = threadIdx.x;
    for (int idx = tid; idx < 1024; idx += 256) {
        int co = idx >> 5, ci = idx & 31;
        s_w[co][ci] = make_float4(gcw[co * 96 + ci], gcw[co * 96 + 32 + ci],
                                  gcw[co * 96 + 64 + ci], 0.f);
    }
    if (tid < 32) {
        s_b[tid] = gcb[tid];
        s_sc[tid] = bng[tid] * rsqrtf(1.f + 1e-5f);
        s_sh[tid] = bnb[tid];
    }
    const __half* mb = m + ((long)(b * L1 + l) * 32) * 1024 + n0;
    const float* xb = x12 + ((long)(b * L1 + l) * 32) * 2048 + n0;
    for (int idx = tid; idx < 2048; idx += 256) {
        int ci = idx >> 6, nl = idx & 63;
        s_in[0][ci][nl] = __half2float(mb[(long)ci * 1024 + nl]);
        s_in[1][ci][nl] = xb[(long)ci * 2048 + nl];
        s_in[2][ci][nl] = xb[(long)ci * 2048 + 1024 + nl];
    }
    __syncthreads();
    int nl = tid & 63, cg = tid >> 6;
    float acc[8];
#pragma unroll
    for (int u = 0; u < 8; u++) acc[u] = s_b[cg * 8 + u];
#pragma unroll
    for (int ci = 0; ci < 32; ci++) {
        float v0 = s_in[0][ci][nl], v1 = s_in[1][ci][nl], v2 = s_in[2][ci][nl];
#pragma unroll
        for (int u = 0; u < 8; u++) {
            float4 w = s_w[cg * 8 + u][ci];
            acc[u] += w.x * v0 + w.y * v1 + w.z * v2;
        }
    }
    const float* rb = hold + ((long)(b * L0 + l + d) * 32) * 1024 + n0 + nl;
    float* ob = hnew + ((long)(b * L1 + l) * 32) * 1024 + n0 + nl;
#pragma unroll
    for (int u = 0; u < 8; u++) {
        int co = cg * 8 + u;
        float res = rb[(long)co * 1024];
        ob[(long)co * 1024] = (acc[u] + res) * s_sc[co] + s_sh[co];
    }
}

// ---------------------------------------------------------------------------
// prep: concat skip weights (half) + summed skip bias; round end1_w to half
// ---------------------------------------------------------------------------
__global__ __launch_bounds__(256) void k_prep(const float* __restrict__ skw,
                                              const float* __restrict__ skb,
                                              __half* __restrict__ wcat,
                                              float* __restrict__ bsum) {
    int co = blockIdx.x, k = threadIdx.x;
    int i = k >> 5, ci = k & 31;
    wcat[co * 256 + k] = __float2half(skw[((long)i * 256 + co) * 32 + ci]);
    if (k == 0) {
        float s = 0.f;
#pragma unroll
        for (int j = 0; j < 8; j++) s += skb[j * 256 + co];
        bsum[co] = s;
    }
}
__global__ __launch_bounds__(256) void k_roundh(const float* __restrict__ w,
                                                __half* __restrict__ o) {
    int i = blockIdx.x * 256 + threadIdx.x;
    o[i] = __float2half(w[i]);
}

// ---------------------------------------------------------------------------
__global__ __launch_bounds__(256) void k_end2(const float* __restrict__ e1,
                                              const float* __restrict__ w2,
                                              const float* __restrict__ b2,
                                              float* __restrict__ out) {
    __shared__ float s_w[12 * 512];
    int tid = threadIdx.x;
    for (int idx = tid; idx < 6144; idx += 256) s_w[idx] = w2[idx];
    __syncthreads();
    int col = blockIdx.x * 256 + tid;
    int b = col >> 10, n = col & 1023;
    float acc[12];
#pragma unroll
    for (int o = 0; o < 12; o++) acc[o] = b2[o];
    for (int c = 0; c < 512; c++) {
        float v = e1[(long)c * 65536 + col];
#pragma unroll
        for (int o = 0; o < 12; o++) acc[o] += s_w[o * 512 + c] * v;
    }
#pragma unroll
    for (int o = 0; o < 12; o++) out[((long)b * 12 + o) * 1024 + n] = acc[o];
}

// ---------------------------------------------------------------------------
extern "C" void kernel_launch(void* const* d_in, const int* in_sizes, int n_in,
                              void* d_out, int out_size) {
    const float* x        = (const float*)d_in[0];
    const float* start_w  = (const float*)d_in[1];
    const float* start_b  = (const float*)d_in[2];
    const float* nodevec1 = (const float*)d_in[3];
    const float* nodevec2 = (const float*)d_in[4];
    const float* filter_w = (const float*)d_in[5];
    const float* filter_b = (const float*)d_in[6];
    const float* gate_w   = (const float*)d_in[7];
    const float* gate_b   = (const float*)d_in[8];
    const float* skip_w   = (const float*)d_in[9];
    const float* skip_b   = (const float*)d_in[10];
    const float* gc_w     = (const float*)d_in[11];
    const float* gc_b     = (const float*)d_in[12];
    const float* bn_g     = (const float*)d_in[13];
    const float* bn_b     = (const float*)d_in[14];
    const float* end1_w   = (const float*)d_in[15];
    const float* end1_b   = (const float*)d_in[16];
    const float* end2_w   = (const float*)d_in[17];
    const float* end2_b   = (const float*)d_in[18];

    float *hA, *hB, *x12, *adpf, *e1, *bsk;
    __half *m, *Bm, *msk, *skip, *w1r, *wsk;
    cudaGetSymbolAddress((void**)&hA, g_hA);
    cudaGetSymbolAddress((void**)&hB, g_hB);
    cudaGetSymbolAddress((void**)&m, g_m);
    cudaGetSymbolAddress((void**)&x12, g_x12);
    cudaGetSymbolAddress((void**)&adpf, g_adpf);
    cudaGetSymbolAddress((void**)&Bm, g_Bm);
    cudaGetSymbolAddress((void**)&msk, g_msk);
    cudaGetSymbolAddress((void**)&skip, g_skip);
    cudaGetSymbolAddress((void**)&e1, g_e1);
    cudaGetSymbolAddress((void**)&w1r, g_w1r);
    cudaGetSymbolAddress((void**)&wsk, g_wsk);
    cudaGetSymbolAddress((void**)&bsk, g_bsk);

    k_adp<<<1024, 256>>>(nodevec1, nodevec2, adpf, Bm);
    k_sgemm<<<dim3(8, 8), 256>>>(adpf, adpf, Bm);
    k_start<<<dim3(64 * 13, 4), 256>>>(x, start_w, start_b, hA);
    k_roundh<<<512, 256>>>(end1_w, w1r);
    k_prep<<<256, 256>>>(skip_w, skip_b, wsk, bsk);

    const int lens[9] = {13, 12, 10, 9, 7, 6, 4, 3, 1};
    const int dil[8]  = {1, 2, 1, 2, 1, 2, 1, 2};
    float* hcur = hA;
    float* hnext = hB;

    for (int i = 0; i < 8; i++) {
        int L0 = lens[i], L1 = lens[i + 1], d = dil[i];
        k_dconv<<<dim3(64 * L1, 16), 256>>>(hcur,
                                            filter_w + i * 2048, filter_b + i * 32,
                                            gate_w + i * 2048, gate_b + i * 32,
                                            m, msk, L0, L1, d, i);
        if (i < 7) {
            int M = 2048 * L1;
            // x12 = m @ [ADP | ADP^2]
            k_gemm_f16<<<dim3(2048 / 256, M / 128), 256>>>(
                m, (const half2*)Bm, x12, 1024, 1024, 2048, 2048, nullptr, 0);
            k_gc<<<dim3(64 * L1, 16), 256>>>(m, x12, hcur,
                                             gc_w + i * 32 * 96, gc_b + i * 32,
                                             bn_g + i * 32, bn_b + i * 32,
                                             hnext, L0, L1, d);
            float* t = hcur; hcur = hnext; hnext = t;
        }
    }

    // skip = relu(Wcat @ msk + bsum), stored k-packed half
    k_gemm_f16<<<dim3(65536 / 256, 2), 256>>>(
        wsk, (const half2*)msk, skip, 256, 256, 65536, 65536, bsk, 2 | 4);
    // e1 = relu(W1 @ skip + b1), fp32
    k_gemm_f16<<<dim3(65536 / 256, 4), 256>>>(
        w1r, (const half2*)skip, e1, 256, 256, 65536, 65536, end1_b, 2);
    k_end2<<<256, 256>>>(e1, end2_w, end2_b, (float*)d_out);
}

// round 11
// speedup vs baseline: 1.0082x; 1.0081x over previous
#include <cuda_runtime.h>
#include <cuda_fp16.h>
#include <math.h>
#include <stdint.h>

// ---------------------------------------------------------------------------
// GWNet2: B=64, N=1024, L=13, RC=DC=32, SC=256, EC=512, OUT=12, LAYERS=8
// h layout: [B][L][C][N] fp32.
// Per layer: dconv computes m (regs), premixes mm0=Wm@m+gcb, mm1=W1@m, mm2=W2@m
// (channel/node mixes commute: W1@(m@ADP) = (W1@m)@ADP). GEMM computes
// [mm1|mm2] @ [ADP;ADP2] and fuses the gc tail in its epilogue:
//   hnew = (acc + mm0 + hold)*bn_scale + bn_shift.   (k_gc + x12 eliminated)
// GEMMs: mma.sync m16n8k16 f16 in, f32 acc. B operands k-packed half2.
// ---------------------------------------------------------------------------

__device__ float  g_hA  [64 * 13 * 32 * 1024];
__device__ float  g_hB  [64 * 12 * 32 * 1024];
__device__ __half g_mmA [64 * 12 * 32 * 2048];       // [mm1 | mm2], A operand
__device__ __half g_mm0 [64 * 12 * 32 * 1024];       // Wm@m + gcb
__device__ float  g_adpf[1024 * 1024];               // ADP fp32 (for ADP^2)
__device__ __half g_Bm  [2048 * 1024];               // k-packed [ADP ; ADP^2]
__device__ __half g_msk [256 * 65536];               // k-packed concat m_last
__device__ __half g_skip[256 * 65536];               // k-packed relu(skip)
__device__ __half g_e1  [512 * 65536];               // half now
__device__ __half g_w1r [512 * 256];
__device__ __half g_wsk [256 * 256];
__device__ float  g_bsk [256];

// ---------------------------------------------------------------------------
__device__ __forceinline__ void cp16(void* smem, const void* g) {
    unsigned s = (unsigned)__cvta_generic_to_shared(smem);
    asm volatile("cp.async.cg.shared.global [%0], [%1], 16;\n" :: "r"(s), "l"(g));
}

// ---------------------------------------------------------------------------
// adp = softmax(relu(nv1 @ nv2)) -> fp32 adpf + k-packed half rows 0..511
// ---------------------------------------------------------------------------
__global__ __launch_bounds__(256) void k_adp(const float* __restrict__ nv1,
                                             const float* __restrict__ nv2,
                                             float* __restrict__ adpf,
                                             __half* __restrict__ Bpk) {
    __shared__ float red[256];
    int v = blockIdx.x, tid = threadIdx.x;
    float n1[10];
#pragma unroll
    for (int k = 0; k < 10; k++) n1[k] = nv1[v * 10 + k];
    float a[4];
#pragma unroll
    for (int j = 0; j < 4; j++) {
        int w = tid + j * 256;
        float s = 0.f;
#pragma unroll
        for (int k = 0; k < 10; k++) s += n1[k] * nv2[k * 1024 + w];
        a[j] = fmaxf(s, 0.f);
    }
    float mx = fmaxf(fmaxf(a[0], a[1]), fmaxf(a[2], a[3]));
    red[tid] = mx; __syncthreads();
    for (int s = 128; s > 0; s >>= 1) {
        if (tid < s) red[tid] = fmaxf(red[tid], red[tid + s]);
        __syncthreads();
    }
    mx = red[0]; __syncthreads();
    float e[4]; float sum = 0.f;
#pragma unroll
    for (int j = 0; j < 4; j++) { e[j] = expf(a[j] - mx); sum += e[j]; }
    red[tid] = sum; __syncthreads();
    for (int s = 128; s > 0; s >>= 1) {
        if (tid < s) red[tid] += red[tid + s];
        __syncthreads();
    }
    float inv = 1.f / red[0];
#pragma unroll
    for (int j = 0; j < 4; j++) {
        int w = tid + j * 256;
        float val = e[j] * inv;
        adpf[(long)v * 1024 + w] = val;
        Bpk[((long)(v >> 1) * 1024 + w) * 2 + (v & 1)] = __float2half(val);
    }
}

// ---------------------------------------------------------------------------
__global__ __launch_bounds__(256) void k_start(const float* __restrict__ x,
                                               const float* __restrict__ sw,
                                               const float* __restrict__ sb,
                                               float* __restrict__ h) {
    int bl = blockIdx.x;
    int b = bl / 13, l = bl - b * 13;
    int n = blockIdx.y * 256 + threadIdx.x;
    float x0 = x[(((long)b * 2 + 0) * 1024 + n) * 13 + l];
    float x1 = x[(((long)b * 2 + 1) * 1024 + n) * 13 + l];
    float* hb = h + ((long)(b * 13 + l) * 32) * 1024 + n;
#pragma unroll
    for (int c = 0; c < 32; c++)
        hb[(long)c * 1024] = sw[c * 2] * x0 + sw[c * 2 + 1] * x1 + sb[c];
}

// ---------------------------------------------------------------------------
// dilated conv + tanh*sigmoid + gc channel premix.
// Outputs (doPre): mm0 = Wm@m+gcb (half), mmA = [W1@m | W2@m] (half).
// Last timestep m also k-packed into msk.
// ---------------------------------------------------------------------------
__global__ __launch_bounds__(256) void k_dconv(const float* __restrict__ h,
                                               const float* __restrict__ fw,
                                               const float* __restrict__ fb,
                                               const float* __restrict__ gw,
                                               const float* __restrict__ gb,
                                               const float* __restrict__ gcw,
                                               const float* __restrict__ gcb,
                                               __half* __restrict__ mmA,
                                               __half* __restrict__ mm0,
                                               __half* __restrict__ msk,
                                               int L0, int L1, int d, int layer,
                                               int doPre) {
    __shared__ float s_in[2][32][64];
    __shared__ float4 s_w[32][32];
    __shared__ float4 s_w2[32][32];
    __shared__ float s_m[32][64];
    __shared__ float s_fb[32], s_gb[32], s_gcb[32];
    int bl = blockIdx.x;
    int b = bl / L1, l = bl - b * L1;
    int n0 = blockIdx.y * 64;
    int tid = threadIdx.x;
    for (int idx = tid; idx < 1024; idx += 256) {
        int co = idx >> 5, ci = idx & 31;
        int o = (co * 32 + ci) * 2;
        s_w[co][ci] = make_float4(fw[o], fw[o + 1], gw[o], gw[o + 1]);
        if (doPre)
            s_w2[co][ci] = make_float4(gcw[co * 96 + ci], gcw[co * 96 + 32 + ci],
                                       gcw[co * 96 + 64 + ci], 0.f);
    }
    if (tid < 32) {
        s_fb[tid] = fb[tid]; s_gb[tid] = gb[tid];
        s_gcb[tid] = doPre ? gcb[tid] : 0.f;
    }
    const float* hb = h + ((long)(b * L0 + l) * 32) * 1024 + n0;
    for (int idx = tid; idx < 4096; idx += 256) {
        int tap = idx >> 11, ci = (idx >> 6) & 31, nl = idx & 63;
        s_in[tap][ci][nl] = hb[((long)(tap * d) * 32 + ci) * 1024 + nl];
    }
    __syncthreads();
    int nl = tid & 63, cg = tid >> 6;
    float fa[8], ga[8];
#pragma unroll
    for (int u = 0; u < 8; u++) { fa[u] = s_fb[cg * 8 + u]; ga[u] = s_gb[cg * 8 + u]; }
#pragma unroll
    for (int ci = 0; ci < 32; ci++) {
        float v0 = s_in[0][ci][nl], v1 = s_in[1][ci][nl];
#pragma unroll
        for (int u = 0; u < 8; u++) {
            float4 w = s_w[cg * 8 + u][ci];
            fa[u] += w.x * v0 + w.y * v1;
            ga[u] += w.z * v0 + w.w * v1;
        }
    }
    bool last = (l == L1 - 1);
    long col = (long)b * 1024 + n0 + nl;
    float mval[8];
#pragma unroll
    for (int u = 0; u < 8; u++) {
        mval[u] = tanhf(fa[u]) * (1.f / (1.f + expf(-ga[u])));
        if (last) {
            int k = layer * 32 + cg * 8 + u;
            msk[((long)(k >> 1) * 65536 + col) * 2 + (k & 1)] =
                __float2half(mval[u]);
        }
    }
    if (!doPre) return;
    // stage m for premix
#pragma unroll
    for (int u = 0; u < 8; u++) s_m[cg * 8 + u][nl] = mval[u];
    __syncthreads();
    float p0[8], p1[8], p2[8];
#pragma unroll
    for (int u = 0; u < 8; u++) { p0[u] = s_gcb[cg * 8 + u]; p1[u] = 0.f; p2[u] = 0.f; }
#pragma unroll
    for (int ci = 0; ci < 32; ci++) {
        float v = s_m[ci][nl];
#pragma unroll
        for (int u = 0; u < 8; u++) {
            float4 w = s_w2[cg * 8 + u][ci];
            p0[u] += w.x * v; p1[u] += w.y * v; p2[u] += w.z * v;
        }
    }
    long rowbase = (long)(b * L1 + l) * 32;
#pragma unroll
    for (int u = 0; u < 8; u++) {
        long row = rowbase + cg * 8 + u;
        mm0[row * 1024 + n0 + nl] = __float2half(p0[u]);
        mmA[row * 2048 + n0 + nl] = __float2half(p1[u]);
        mmA[row * 2048 + 1024 + n0 + nl] = __float2half(p2[u]);
    }
}

// ---------------------------------------------------------------------------
// fp32 SIMT SGEMM: ADP^2 = ADP @ ADP; k-packed half into Bpk rows 512..1023
// ---------------------------------------------------------------------------
__global__ __launch_bounds__(256) void k_sgemm(const float* __restrict__ A,
                                               const float* __restrict__ B,
                                               __half* __restrict__ Bpk) {
    __shared__ float As[16][132];
    __shared__ float Bs[16][128];
    int tid = threadIdx.x;
    int m0 = blockIdx.y * 128, n0 = blockIdx.x * 128;
    int ty = tid >> 4, tx = tid & 15;
    float acc[8][8];
#pragma unroll
    for (int i = 0; i < 8; i++)
#pragma unroll
        for (int j = 0; j < 8; j++) acc[i][j] = 0.f;

    for (int k0 = 0; k0 < 1024; k0 += 16) {
#pragma unroll
        for (int i = 0; i < 2; i++) {
            int f = tid + i * 256;
            int r = f >> 2, kc = (f & 3) * 4;
            float4 v = *(const float4*)(A + (long)(m0 + r) * 1024 + k0 + kc);
            As[kc + 0][r] = v.x; As[kc + 1][r] = v.y;
            As[kc + 2][r] = v.z; As[kc + 3][r] = v.w;
        }
#pragma unroll
        for (int i = 0; i < 2; i++) {
            int f = tid + i * 256;
            int r = f >> 5, nc = (f & 31) * 4;
            float4 v = *(const float4*)(B + (long)(k0 + r) * 1024 + n0 + nc);
            *(float4*)&Bs[r][nc] = v;
        }
        __syncthreads();
#pragma unroll
        for (int k = 0; k < 16; k++) {
            float a[8], b[8];
            float4 a0 = *(const float4*)&As[k][ty * 8];
            float4 a1 = *(const float4*)&As[k][ty * 8 + 4];
            a[0] = a0.x; a[1] = a0.y; a[2] = a0.z; a[3] = a0.w;
            a[4] = a1.x; a[5] = a1.y; a[6] = a1.z; a[7] = a1.w;
            float4 b0 = *(const float4*)&Bs[k][tx * 8];
            float4 b1 = *(const float4*)&Bs[k][tx * 8 + 4];
            b[0] = b0.x; b[1] = b0.y; b[2] = b0.z; b[3] = b0.w;
            b[4] = b1.x; b[5] = b1.y; b[6] = b1.z; b[7] = b1.w;
#pragma unroll
            for (int i = 0; i < 8; i++)
#pragma unroll
                for (int j = 0; j < 8; j++) acc[i][j] += a[i] * b[j];
        }
        __syncthreads();
    }
#pragma unroll
    for (int i = 0; i < 8; i++) {
        int v = m0 + ty * 8 + i;   // k row (within ADP^2 block)
#pragma unroll
        for (int j = 0; j < 8; j++) {
            int w = n0 + tx * 8 + j;
            Bpk[((long)(512 + (v >> 1)) * 1024 + w) * 2 + (v & 1)] =
                __float2half(acc[i][j]);
        }
    }
}

// ---------------------------------------------------------------------------
// fused layer GEMM + gc tail. C_acc = mmA[M,2048] @ Bpk[2048,1024];
// hnew = (acc + mm0 + hold)*sc + sh. CTA 128x256, warp tile 64x64.
// ---------------------------------------------------------------------------
__global__ __launch_bounds__(256) void k_gemm_gc(const __half* __restrict__ A,
                                                 const half2* __restrict__ Bpk,
                                                 float* __restrict__ hnew,
                                                 const float* __restrict__ hold,
                                                 const __half* __restrict__ mm0,
                                                 const float* __restrict__ bng,
                                                 const float* __restrict__ bnb,
                                                 int L0, int L1, int d) {
    __shared__ __half As[2][128][40];
    __shared__ half2  Bs[2][16][264];
    int tid = threadIdx.x;
    int m0 = blockIdx.y * 128;
    int n0 = blockIdx.x * 256;
    int w = tid >> 5, lane = tid & 31;
    int grp = lane >> 2, tg = lane & 3;
    int wm = (w & 1) * 64, wn = (w >> 1) * 64;

    float acc[4][8][4];
#pragma unroll
    for (int mt = 0; mt < 4; mt++)
#pragma unroll
        for (int nt = 0; nt < 8; nt++)
#pragma unroll
            for (int c = 0; c < 4; c++) acc[mt][nt][c] = 0.f;

    const int nstage = 2048 / 32;
    {
#pragma unroll
        for (int i = 0; i < 2; i++) {
            int ch = tid + i * 256;
            int r = ch >> 2, p = (ch & 3) * 8;
            cp16(&As[0][r][p], A + (long)(m0 + r) * 2048 + p);
        }
#pragma unroll
        for (int i = 0; i < 4; i++) {
            int ch = tid + i * 256;
            int r = ch >> 6, c4 = (ch & 63) * 4;
            cp16(&Bs[0][r][c4], Bpk + (long)r * 1024 + n0 + c4);
        }
        asm volatile("cp.async.commit_group;\n");
    }

    for (int s = 0; s < nstage; s++) {
        int buf = s & 1;
        if (s + 1 < nstage) {
            int nb = buf ^ 1;
            int k0 = (s + 1) * 32;
#pragma unroll
            for (int i = 0; i < 2; i++) {
                int ch = tid + i * 256;
                int r = ch >> 2, p = (ch & 3) * 8;
                cp16(&As[nb][r][p], A + (long)(m0 + r) * 2048 + k0 + p);
            }
#pragma unroll
            for (int i = 0; i < 4; i++) {
                int ch = tid + i * 256;
                int r = ch >> 6, c4 = (ch & 63) * 4;
                cp16(&Bs[nb][r][c4], Bpk + (long)(k0 / 2 + r) * 1024 + n0 + c4);
            }
            asm volatile("cp.async.commit_group;\n");
            asm volatile("cp.async.wait_group 1;\n");
        } else {
            asm volatile("cp.async.wait_group 0;\n");
        }
        __syncthreads();

#pragma unroll
        for (int s2 = 0; s2 < 2; s2++) {
            unsigned a[4][4];
#pragma unroll
            for (int mt = 0; mt < 4; mt++) {
                int rb = wm + mt * 16;
                a[mt][0] = *(const unsigned*)&As[buf][rb + grp][s2 * 16 + tg * 2];
                a[mt][1] = *(const unsigned*)&As[buf][rb + grp + 8][s2 * 16 + tg * 2];
                a[mt][2] = *(const unsigned*)&As[buf][rb + grp][s2 * 16 + tg * 2 + 8];
                a[mt][3] = *(const unsigned*)&As[buf][rb + grp + 8][s2 * 16 + tg * 2 + 8];
            }
            unsigned b[8][2];
#pragma unroll
            for (int nt = 0; nt < 8; nt++) {
                int cb = wn + nt * 8 + grp;
                b[nt][0] = *(const unsigned*)&Bs[buf][s2 * 8 + tg][cb];
                b[nt][1] = *(const unsigned*)&Bs[buf][s2 * 8 + tg + 4][cb];
            }
#pragma unroll
            for (int mt = 0; mt < 4; mt++)
#pragma unroll
                for (int nt = 0; nt < 8; nt++) {
                    asm volatile(
                        "mma.sync.aligned.m16n8k16.row.col.f32.f16.f16.f32 "
                        "{%0,%1,%2,%3}, {%4,%5,%6,%7}, {%8,%9}, {%0,%1,%2,%3};\n"
                        : "+f"(acc[mt][nt][0]), "+f"(acc[mt][nt][1]),
                          "+f"(acc[mt][nt][2]), "+f"(acc[mt][nt][3])
                        : "r"(a[mt][0]), "r"(a[mt][1]), "r"(a[mt][2]), "r"(a[mt][3]),
                          "r"(b[nt][0]), "r"(b[nt][1]));
                }
        }
        __syncthreads();
    }

    const float rs = rsqrtf(1.f + 1e-5f);
#pragma unroll
    for (int mt = 0; mt < 4; mt++) {
        int row0 = m0 + wm + mt * 16 + grp;
        int row1 = row0 + 8;
        int blx = row0 >> 5;
        int b = blx / L1, l = blx - b * L1;
        long hbase = (long)(b * L0 + l + d) * 32;
        int co0 = row0 & 31, co1 = row1 & 31;
        float sc0 = bng[co0] * rs, sh0 = bnb[co0];
        float sc1 = bng[co1] * rs, sh1 = bnb[co1];
#pragma unroll
        for (int nt = 0; nt < 8; nt++) {
            int col = n0 + wn + nt * 8 + tg * 2;
            half2 q0 = *(const half2*)&mm0[(long)row0 * 1024 + col];
            half2 q1 = *(const half2*)&mm0[(long)row1 * 1024 + col];
            float2 r0 = *(const float2*)&hold[(hbase + co0) * 1024 + col];
            float2 r1 = *(const float2*)&hold[(hbase + co1) * 1024 + col];
            float2 o0, o1;
            o0.x = (acc[mt][nt][0] + __half2float(q0.x) + r0.x) * sc0 + sh0;
            o0.y = (acc[mt][nt][1] + __half2float(q0.y) + r0.y) * sc0 + sh0;
            o1.x = (acc[mt][nt][2] + __half2float(q1.x) + r1.x) * sc1 + sh1;
            o1.y = (acc[mt][nt][3] + __half2float(q1.y) + r1.y) * sc1 + sh1;
            *(float2*)&hnew[(long)row0 * 1024 + col] = o0;
            *(float2*)&hnew[(long)row1 * 1024 + col] = o1;
        }
    }
}

// ---------------------------------------------------------------------------
// generic fp16 GEMM (skip/end1). flags bit1: +bias relu. bit2: C k-packed half.
// bit3: C plain half. else fp32.
// ---------------------------------------------------------------------------
__global__ __launch_bounds__(256) void k_gemm_f16(const __half* __restrict__ A,
                                                  const half2* __restrict__ Bpk,
                                                  void* __restrict__ Cv,
                                                  int K, int lda, long ldb2, long ldc,
                                                  const float* __restrict__ bias,
                                                  int flags) {
    __shared__ __half As[2][128][40];
    __shared__ half2  Bs[2][16][264];
    int tid = threadIdx.x;
    int m0 = blockIdx.y * 128;
    long n0 = (long)blockIdx.x * 256;
    int w = tid >> 5, lane = tid & 31;
    int grp = lane >> 2, tg = lane & 3;
    int wm = (w & 1) * 64, wn = (w >> 1) * 64;

    float acc[4][8][4];
#pragma unroll
    for (int mt = 0; mt < 4; mt++)
#pragma unroll
        for (int nt = 0; nt < 8; nt++)
#pragma unroll
            for (int c = 0; c < 4; c++) acc[mt][nt][c] = 0.f;

    int nstage = K / 32;
    {
#pragma unroll
        for (int i = 0; i < 2; i++) {
            int ch = tid + i * 256;
            int r = ch >> 2, p = (ch & 3) * 8;
            cp16(&As[0][r][p], A + (long)(m0 + r) * lda + p);
        }
#pragma unroll
        for (int i = 0; i < 4; i++) {
            int ch = tid + i * 256;
            int r = ch >> 6, c4 = (ch & 63) * 4;
            cp16(&Bs[0][r][c4], Bpk + (long)r * ldb2 + n0 + c4);
        }
        asm volatile("cp.async.commit_group;\n");
    }

    for (int s = 0; s < nstage; s++) {
        int buf = s & 1;
        if (s + 1 < nstage) {
            int nb = buf ^ 1;
            int k0 = (s + 1) * 32;
#pragma unroll
            for (int i = 0; i < 2; i++) {
                int ch = tid + i * 256;
                int r = ch >> 2, p = (ch & 3) * 8;
                cp16(&As[nb][r][p], A + (long)(m0 + r) * lda + k0 + p);
            }
#pragma unroll
            for (int i = 0; i < 4; i++) {
                int ch = tid + i * 256;
                int r = ch >> 6, c4 = (ch & 63) * 4;
                cp16(&Bs[nb][r][c4], Bpk + (long)(k0 / 2 + r) * ldb2 + n0 + c4);
            }
            asm volatile("cp.async.commit_group;\n");
            asm volatile("cp.async.wait_group 1;\n");
        } else {
            asm volatile("cp.async.wait_group 0;\n");
        }
        __syncthreads();

#pragma unroll
        for (int s2 = 0; s2 < 2; s2++) {
            unsigned a[4][4];
#pragma unroll
            for (int mt = 0; mt < 4; mt++) {
                int rb = wm + mt * 16;
                a[mt][0] = *(const unsigned*)&As[buf][rb + grp][s2 * 16 + tg * 2];
                a[mt][1] = *(const unsigned*)&As[buf][rb + grp + 8][s2 * 16 + tg * 2];
                a[mt][2] = *(const unsigned*)&As[buf][rb + grp][s2 * 16 + tg * 2 + 8];
                a[mt][3] = *(const unsigned*)&As[buf][rb + grp + 8][s2 * 16 + tg * 2 + 8];
            }
            unsigned b[8][2];
#pragma unroll
            for (int nt = 0; nt < 8; nt++) {
                int cb = wn + nt * 8 + grp;
                b[nt][0] = *(const unsigned*)&Bs[buf][s2 * 8 + tg][cb];
                b[nt][1] = *(const unsigned*)&Bs[buf][s2 * 8 + tg + 4][cb];
            }
#pragma unroll
            for (int mt = 0; mt < 4; mt++)
#pragma unroll
                for (int nt = 0; nt < 8; nt++) {
                    asm volatile(
                        "mma.sync.aligned.m16n8k16.row.col.f32.f16.f16.f32 "
                        "{%0,%1,%2,%3}, {%4,%5,%6,%7}, {%8,%9}, {%0,%1,%2,%3};\n"
                        : "+f"(acc[mt][nt][0]), "+f"(acc[mt][nt][1]),
                          "+f"(acc[mt][nt][2]), "+f"(acc[mt][nt][3])
                        : "r"(a[mt][0]), "r"(a[mt][1]), "r"(a[mt][2]), "r"(a[mt][3]),
                          "r"(b[nt][0]), "r"(b[nt][1]));
                }
        }
        __syncthreads();
    }

    float* Cf = (float*)Cv;
    __half* Ch = (__half*)Cv;
#pragma unroll
    for (int mt = 0; mt < 4; mt++) {
        int row0 = m0 + wm + mt * 16 + grp;
        int row1 = row0 + 8;
        float b0 = 0.f, b1 = 0.f;
        if (flags & 2) { b0 = bias[row0]; b1 = bias[row1]; }
#pragma unroll
        for (int nt = 0; nt < 8; nt++) {
            long col = n0 + wn + nt * 8 + tg * 2;
            float v00 = acc[mt][nt][0], v01 = acc[mt][nt][1];
            float v10 = acc[mt][nt][2], v11 = acc[mt][nt][3];
            if (flags & 2) {
                v00 = fmaxf(v00 + b0, 0.f); v01 = fmaxf(v01 + b0, 0.f);
                v10 = fmaxf(v10 + b1, 0.f); v11 = fmaxf(v11 + b1, 0.f);
            }
            if (flags & 4) {
                long p0 = ((long)(row0 >> 1) * ldc + col) * 2 + (row0 & 1);
                long p1 = ((long)(row1 >> 1) * ldc + col) * 2 + (row1 & 1);
                Ch[p0] = __float2half(v00); Ch[p0 + 2] = __float2half(v01);
                Ch[p1] = __float2half(v10); Ch[p1 + 2] = __float2half(v11);
            } else if (flags & 8) {
                *(half2*)(Ch + (long)row0 * ldc + col) = __floats2half2_rn(v00, v01);
                *(half2*)(Ch + (long)row1 * ldc + col) = __floats2half2_rn(v10, v11);
            } else {
                *(float2*)(Cf + (long)row0 * ldc + col) = make_float2(v00, v01);
                *(float2*)(Cf + (long)row1 * ldc + col) = make_float2(v10, v11);
            }
        }
    }
}

// ---------------------------------------------------------------------------
__global__ __launch_bounds__(256) void k_prep(const float* __restrict__ skw,
                                              const float* __restrict__ skb,
                                              __half* __restrict__ wcat,
                                              float* __restrict__ bsum) {
    int co = blockIdx.x, k = threadIdx.x;
    int i = k >> 5, ci = k & 31;
    wcat[co * 256 + k] = __float2half(skw[((long)i * 256 + co) * 32 + ci]);
    if (k == 0) {
        float s = 0.f;
#pragma unroll
        for (int j = 0; j < 8; j++) s += skb[j * 256 + co];
        bsum[co] = s;
    }
}
__global__ __launch_bounds__(256) void k_roundh(const float* __restrict__ w,
                                                __half* __restrict__ o) {
    int i = blockIdx.x * 256 + threadIdx.x;
    o[i] = __float2half(w[i]);
}

// ---------------------------------------------------------------------------
__global__ __launch_bounds__(256) void k_end2(const __half* __restrict__ e1,
                                              const float* __restrict__ w2,
                                              const float* __restrict__ b2,
                                              float* __restrict__ out) {
    __shared__ float s_w[12 * 512];
    int tid = threadIdx.x;
    for (int idx = tid; idx < 6144; idx += 256) s_w[idx] = w2[idx];
    __syncthreads();
    int col = blockIdx.x * 256 + tid;
    int b = col >> 10, n = col & 1023;
    float acc[12];
#pragma unroll
    for (int o = 0; o < 12; o++) acc[o] = b2[o];
    for (int c = 0; c < 512; c++) {
        float v = __half2float(e1[(long)c * 65536 + col]);
#pragma unroll
        for (int o = 0; o < 12; o++) acc[o] += s_w[o * 512 + c] * v;
    }
#pragma unroll
    for (int o = 0; o < 12; o++) out[((long)b * 12 + o) * 1024 + n] = acc[o];
}

// ---------------------------------------------------------------------------
extern "C" void kernel_launch(void* const* d_in, const int* in_sizes, int n_in,
                              void* d_out, int out_size) {
    const float* x        = (const float*)d_in[0];
    const float* start_w  = (const float*)d_in[1];
    const float* start_b  = (const float*)d_in[2];
    const float* nodevec1 = (const float*)d_in[3];
    const float* nodevec2 = (const float*)d_in[4];
    const float* filter_w = (const float*)d_in[5];
    const float* filter_b = (const float*)d_in[6];
    const float* gate_w   = (const float*)d_in[7];
    const float* gate_b   = (const float*)d_in[8];
    const float* skip_w   = (const float*)d_in[9];
    const float* skip_b   = (const float*)d_in[10];
    const float* gc_w     = (const float*)d_in[11];
    const float* gc_b     = (const float*)d_in[12];
    const float* bn_g     = (const float*)d_in[13];
    const float* bn_b     = (const float*)d_in[14];
    const float* end1_w   = (const float*)d_in[15];
    const float* end1_b   = (const float*)d_in[16];
    const float* end2_w   = (const float*)d_in[17];
    const float* end2_b   = (const float*)d_in[18];

    float *hA, *hB, *adpf, *bsk;
    __half *mmA, *mm0, *Bm, *msk, *skip, *e1, *w1r, *wsk;
    cudaGetSymbolAddress((void**)&hA, g_hA);
    cudaGetSymbolAddress((void**)&hB, g_hB);
    cudaGetSymbolAddress((void**)&mmA, g_mmA);
    cudaGetSymbolAddress((void**)&mm0, g_mm0);
    cudaGetSymbolAddress((void**)&adpf, g_adpf);
    cudaGetSymbolAddress((void**)&Bm, g_Bm);
    cudaGetSymbolAddress((void**)&msk, g_msk);
    cudaGetSymbolAddress((void**)&skip, g_skip);
    cudaGetSymbolAddress((void**)&e1, g_e1);
    cudaGetSymbolAddress((void**)&w1r, g_w1r);
    cudaGetSymbolAddress((void**)&wsk, g_wsk);
    cudaGetSymbolAddress((void**)&bsk, g_bsk);

    k_adp<<<1024, 256>>>(nodevec1, nodevec2, adpf, Bm);
    k_sgemm<<<dim3(8, 8), 256>>>(adpf, adpf, Bm);
    k_start<<<dim3(64 * 13, 4), 256>>>(x, start_w, start_b, hA);
    k_roundh<<<512, 256>>>(end1_w, w1r);
    k_prep<<<256, 256>>>(skip_w, skip_b, wsk, bsk);

    const int lens[9] = {13, 12, 10, 9, 7, 6, 4, 3, 1};
    const int dil[8]  = {1, 2, 1, 2, 1, 2, 1, 2};
    float* hcur = hA;
    float* hnext = hB;

    for (int i = 0; i < 8; i++) {
        int L0 = lens[i], L1 = lens[i + 1], d = dil[i];
        int doPre = (i < 7) ? 1 : 0;
        k_dconv<<<dim3(64 * L1, 16), 256>>>(hcur,
                                            filter_w + i * 2048, filter_b + i * 32,
                                            gate_w + i * 2048, gate_b + i * 32,
                                            gc_w + i * 32 * 96, gc_b + i * 32,
                                            mmA, mm0, msk, L0, L1, d, i, doPre);
        if (i < 7) {
            int M = 2048 * L1;
            // hnew = (mmA @ [ADP;ADP^2] + mm0 + hold)*bn_sc + bn_sh
            k_gemm_gc<<<dim3(4, M / 128), 256>>>(
                mmA, (const half2*)Bm, hnext, hcur, mm0,
                bn_g + i * 32, bn_b + i * 32, L0, L1, d);
            float* t = hcur; hcur = hnext; hnext = t;
        }
    }

    // skip = relu(Wcat @ msk + bsum), k-packed half
    k_gemm_f16<<<dim3(65536 / 256, 2), 256>>>(
        wsk, (const half2*)msk, skip, 256, 256, 65536, 65536, bsk, 2 | 4);
    // e1 = relu(W1 @ skip + b1), plain half
    k_gemm_f16<<<dim3(65536 / 256, 4), 256>>>(
        w1r, (const half2*)skip, e1, 256, 256, 65536, 65536, end1_b, 2 | 8);
    k_end2<<<256, 256>>>(e1, end2_w, end2_b, (float*)d_out);
}

// round 12
// speedup vs baseline: 1.0161x; 1.0078x over previous
#include <cuda_runtime.h>
#include <cuda_fp16.h>
#include <math.h>
#include <stdint.h>

// ---------------------------------------------------------------------------
// GWNet2: B=64, N=1024, L=13, RC=DC=32, SC=256, EC=512, OUT=12, LAYERS=8
// h layout: [B][L][C][N] fp32.
// dconv: packed fp32x2 FMA (fma.rn.f32x2) for conv + gc premix.
// GEMMs: mma.sync m16n8k16 f16 in/f32 acc; A fragments via ldmatrix.x4;
// B operands k-packed half2. gc tail fused into GEMM epilogue.
// ---------------------------------------------------------------------------

__device__ float  g_hA  [64 * 13 * 32 * 1024];
__device__ float  g_hB  [64 * 12 * 32 * 1024];
__device__ __half g_mmA [64 * 12 * 32 * 2048];       // [mm1 | mm2], A operand
__device__ __half g_mm0 [64 * 12 * 32 * 1024];       // Wm@m + gcb
__device__ float  g_adpf[1024 * 1024];               // ADP fp32 (for ADP^2)
__device__ __half g_Bm  [2048 * 1024];               // k-packed [ADP ; ADP^2]
__device__ __half g_msk [256 * 65536];               // k-packed concat m_last
__device__ __half g_skip[256 * 65536];               // k-packed relu(skip)
__device__ __half g_e1  [512 * 65536];
__device__ __half g_w1r [512 * 256];
__device__ __half g_wsk [256 * 256];
__device__ float  g_bsk [256];

// ---------------------------------------------------------------------------
__device__ __forceinline__ void cp16(void* smem, const void* g) {
    unsigned s = (unsigned)__cvta_generic_to_shared(smem);
    asm volatile("cp.async.cg.shared.global [%0], [%1], 16;\n" :: "r"(s), "l"(g));
}
__device__ __forceinline__ unsigned long long packf2(float lo, float hi) {
    unsigned long long r;
    asm("mov.b64 %0, {%1, %2};" : "=l"(r) : "f"(lo), "f"(hi));
    return r;
}
__device__ __forceinline__ void unpackf2(unsigned long long v, float& lo, float& hi) {
    asm("mov.b64 {%0, %1}, %2;" : "=f"(lo), "=f"(hi) : "l"(v));
}
#define FMA2(acc, a, b) \
    asm("fma.rn.f32x2 %0, %1, %2, %0;" : "+l"(acc) : "l"(a), "l"(b))

// ---------------------------------------------------------------------------
// adp = softmax(relu(nv1 @ nv2)) -> fp32 adpf + k-packed half rows 0..511
// ---------------------------------------------------------------------------
__global__ __launch_bounds__(256) void k_adp(const float* __restrict__ nv1,
                                             const float* __restrict__ nv2,
                                             float* __restrict__ adpf,
                                             __half* __restrict__ Bpk) {
    __shared__ float red[256];
    int v = blockIdx.x, tid = threadIdx.x;
    float n1[10];
#pragma unroll
    for (int k = 0; k < 10; k++) n1[k] = nv1[v * 10 + k];
    float a[4];
#pragma unroll
    for (int j = 0; j < 4; j++) {
        int w = tid + j * 256;
        float s = 0.f;
#pragma unroll
        for (int k = 0; k < 10; k++) s += n1[k] * nv2[k * 1024 + w];
        a[j] = fmaxf(s, 0.f);
    }
    float mx = fmaxf(fmaxf(a[0], a[1]), fmaxf(a[2], a[3]));
    red[tid] = mx; __syncthreads();
    for (int s = 128; s > 0; s >>= 1) {
        if (tid < s) red[tid] = fmaxf(red[tid], red[tid + s]);
        __syncthreads();
    }
    mx = red[0]; __syncthreads();
    float e[4]; float sum = 0.f;
#pragma unroll
    for (int j = 0; j < 4; j++) { e[j] = expf(a[j] - mx); sum += e[j]; }
    red[tid] = sum; __syncthreads();
    for (int s = 128; s > 0; s >>= 1) {
        if (tid < s) red[tid] += red[tid + s];
        __syncthreads();
    }
    float inv = 1.f / red[0];
#pragma unroll
    for (int j = 0; j < 4; j++) {
        int w = tid + j * 256;
        float val = e[j] * inv;
        adpf[(long)v * 1024 + w] = val;
        Bpk[((long)(v >> 1) * 1024 + w) * 2 + (v & 1)] = __float2half(val);
    }
}

// ---------------------------------------------------------------------------
__global__ __launch_bounds__(256) void k_start(const float* __restrict__ x,
                                               const float* __restrict__ sw,
                                               const float* __restrict__ sb,
                                               float* __restrict__ h) {
    int bl = blockIdx.x;
    int b = bl / 13, l = bl - b * 13;
    int n = blockIdx.y * 256 + threadIdx.x;
    float x0 = x[(((long)b * 2 + 0) * 1024 + n) * 13 + l];
    float x1 = x[(((long)b * 2 + 1) * 1024 + n) * 13 + l];
    float* hb = h + ((long)(b * 13 + l) * 32) * 1024 + n;
#pragma unroll
    for (int c = 0; c < 32; c++)
        hb[(long)c * 1024] = sw[c * 2] * x0 + sw[c * 2 + 1] * x1 + sb[c];
}

// ---------------------------------------------------------------------------
// dilated conv + tanh*sigmoid + gc channel premix, packed fp32x2 FMA.
// Weights pre-packed per co-pair. Accumulators hold (co_even, co_odd).
// ---------------------------------------------------------------------------
__global__ __launch_bounds__(256) void k_dconv(const float* __restrict__ h,
                                               const float* __restrict__ fw,
                                               const float* __restrict__ fb,
                                               const float* __restrict__ gw,
                                               const float* __restrict__ gb,
                                               const float* __restrict__ gcw,
                                               const float* __restrict__ gcb,
                                               __half* __restrict__ mmA,
                                               __half* __restrict__ mm0,
                                               __half* __restrict__ msk,
                                               int L0, int L1, int d, int layer,
                                               int doPre) {
    __shared__ float  s_in[2][32][64];                 // 16 KB (reused as s_m)
    __shared__ float4 s_wf[32][16];                    // (f0 lo,hi, f1 lo,hi)  8 KB
    __shared__ float4 s_wg[32][16];                    // gate taps             8 KB
    __shared__ float4 s_wpA[32][16];                   // (p0 lo,hi, p1 lo,hi)  8 KB
    __shared__ float2 s_wpB[32][16];                   // (p2 lo,hi)            4 KB
    __shared__ unsigned long long s_fbp[16], s_gbp[16], s_gcbp[16];

    int bl = blockIdx.x;
    int b = bl / L1, l = bl - b * L1;
    int n0 = blockIdx.y * 64;
    int tid = threadIdx.x;

    for (int idx = tid; idx < 512; idx += 256) {
        int ci = idx >> 4, p = idx & 15;
        int co0 = p * 2, co1 = p * 2 + 1;
        int o0 = (co0 * 32 + ci) * 2, o1 = (co1 * 32 + ci) * 2;
        s_wf[ci][p] = make_float4(fw[o0], fw[o1], fw[o0 + 1], fw[o1 + 1]);
        s_wg[ci][p] = make_float4(gw[o0], gw[o1], gw[o0 + 1], gw[o1 + 1]);
        if (doPre) {
            s_wpA[ci][p] = make_float4(gcw[co0 * 96 + ci], gcw[co1 * 96 + ci],
                                       gcw[co0 * 96 + 32 + ci], gcw[co1 * 96 + 32 + ci]);
            s_wpB[ci][p] = make_float2(gcw[co0 * 96 + 64 + ci], gcw[co1 * 96 + 64 + ci]);
        }
    }
    if (tid < 16) {
        s_fbp[tid] = packf2(fb[2 * tid], fb[2 * tid + 1]);
        s_gbp[tid] = packf2(gb[2 * tid], gb[2 * tid + 1]);
        s_gcbp[tid] = doPre ? packf2(gcb[2 * tid], gcb[2 * tid + 1]) : 0ull;
    }
    const float* hb = h + ((long)(b * L0 + l) * 32) * 1024 + n0;
    for (int idx = tid; idx < 4096; idx += 256) {
        int tap = idx >> 11, ci = (idx >> 6) & 31, nl = idx & 63;
        s_in[tap][ci][nl] = hb[((long)(tap * d) * 32 + ci) * 1024 + nl];
    }
    __syncthreads();

    int nl = tid & 63, cg = tid >> 6;
    unsigned long long fa2[4], ga2[4];
#pragma unroll
    for (int p = 0; p < 4; p++) { fa2[p] = s_fbp[cg * 4 + p]; ga2[p] = s_gbp[cg * 4 + p]; }
#pragma unroll
    for (int ci = 0; ci < 32; ci++) {
        float v0 = s_in[0][ci][nl], v1 = s_in[1][ci][nl];
        unsigned long long vv0 = packf2(v0, v0), vv1 = packf2(v1, v1);
#pragma unroll
        for (int p = 0; p < 4; p++) {
            ulonglong2 wf = *(const ulonglong2*)&s_wf[ci][cg * 4 + p];
            FMA2(fa2[p], wf.x, vv0);
            FMA2(fa2[p], wf.y, vv1);
            ulonglong2 wg = *(const ulonglong2*)&s_wg[ci][cg * 4 + p];
            FMA2(ga2[p], wg.x, vv0);
            FMA2(ga2[p], wg.y, vv1);
        }
    }

    bool last = (l == L1 - 1);
    long col = (long)b * 1024 + n0 + nl;
    float mval[8];
#pragma unroll
    for (int p = 0; p < 4; p++) {
        float flo, fhi, glo, ghi;
        unpackf2(fa2[p], flo, fhi);
        unpackf2(ga2[p], glo, ghi);
        mval[2 * p]     = tanhf(flo) * (1.f / (1.f + expf(-glo)));
        mval[2 * p + 1] = tanhf(fhi) * (1.f / (1.f + expf(-ghi)));
    }
#pragma unroll
    for (int u = 0; u < 8; u++) {
        if (last) {
            int k = layer * 32 + cg * 8 + u;
            msk[((long)(k >> 1) * 65536 + col) * 2 + (k & 1)] = __float2half(mval[u]);
        }
    }
    if (!doPre) return;

    // stage m (reuse s_in[0] region — conv reads are done after this sync)
    __syncthreads();
    float (*s_m)[64] = s_in[0];
#pragma unroll
    for (int u = 0; u < 8; u++) s_m[cg * 8 + u][nl] = mval[u];
    __syncthreads();

    unsigned long long p02[4], p12[4], p22[4];
#pragma unroll
    for (int p = 0; p < 4; p++) { p02[p] = s_gcbp[cg * 4 + p]; p12[p] = 0ull; p22[p] = 0ull; }
#pragma unroll
    for (int ci = 0; ci < 32; ci++) {
        float v = s_m[ci][nl];
        unsigned long long vv = packf2(v, v);
#pragma unroll
        for (int p = 0; p < 4; p++) {
            ulonglong2 wa = *(const ulonglong2*)&s_wpA[ci][cg * 4 + p];
            FMA2(p02[p], wa.x, vv);
            FMA2(p12[p], wa.y, vv);
            unsigned long long wb = *(const unsigned long long*)&s_wpB[ci][cg * 4 + p];
            FMA2(p22[p], wb, vv);
        }
    }
    long rowbase = (long)(b * L1 + l) * 32;
#pragma unroll
    for (int p = 0; p < 4; p++) {
        float a0, a1, b0, b1, c0, c1;
        unpackf2(p02[p], a0, a1);
        unpackf2(p12[p], b0, b1);
        unpackf2(p22[p], c0, c1);
        long r0 = rowbase + cg * 8 + 2 * p;
        long r1 = r0 + 1;
        mm0[r0 * 1024 + n0 + nl] = __float2half(a0);
        mm0[r1 * 1024 + n0 + nl] = __float2half(a1);
        mmA[r0 * 2048 + n0 + nl] = __float2half(b0);
        mmA[r1 * 2048 + n0 + nl] = __float2half(b1);
        mmA[r0 * 2048 + 1024 + n0 + nl] = __float2half(c0);
        mmA[r1 * 2048 + 1024 + n0 + nl] = __float2half(c1);
    }
}

// ---------------------------------------------------------------------------
// fp32 SIMT SGEMM: ADP^2 = ADP @ ADP; k-packed half into Bpk rows 512..1023
// ---------------------------------------------------------------------------
__global__ __launch_bounds__(256) void k_sgemm(const float* __restrict__ A,
                                               const float* __restrict__ B,
                                               __half* __restrict__ Bpk) {
    __shared__ float As[16][132];
    __shared__ float Bs[16][128];
    int tid = threadIdx.x;
    int m0 = blockIdx.y * 128, n0 = blockIdx.x * 128;
    int ty = tid >> 4, tx = tid & 15;
    float acc[8][8];
#pragma unroll
    for (int i = 0; i < 8; i++)
#pragma unroll
        for (int j = 0; j < 8; j++) acc[i][j] = 0.f;

    for (int k0 = 0; k0 < 1024; k0 += 16) {
#pragma unroll
        for (int i = 0; i < 2; i++) {
            int f = tid + i * 256;
            int r = f >> 2, kc = (f & 3) * 4;
            float4 v = *(const float4*)(A + (long)(m0 + r) * 1024 + k0 + kc);
            As[kc + 0][r] = v.x; As[kc + 1][r] = v.y;
            As[kc + 2][r] = v.z; As[kc + 3][r] = v.w;
        }
#pragma unroll
        for (int i = 0; i < 2; i++) {
            int f = tid + i * 256;
            int r = f >> 5, nc = (f & 31) * 4;
            float4 v = *(const float4*)(B + (long)(k0 + r) * 1024 + n0 + nc);
            *(float4*)&Bs[r][nc] = v;
        }
        __syncthreads();
#pragma unroll
        for (int k = 0; k < 16; k++) {
            float a[8], b[8];
            float4 a0 = *(const float4*)&As[k][ty * 8];
            float4 a1 = *(const float4*)&As[k][ty * 8 + 4];
            a[0] = a0.x; a[1] = a0.y; a[2] = a0.z; a[3] = a0.w;
            a[4] = a1.x; a[5] = a1.y; a[6] = a1.z; a[7] = a1.w;
            float4 b0 = *(const float4*)&Bs[k][tx * 8];
            float4 b1 = *(const float4*)&Bs[k][tx * 8 + 4];
            b[0] = b0.x; b[1] = b0.y; b[2] = b0.z; b[3] = b0.w;
            b[4] = b1.x; b[5] = b1.y; b[6] = b1.z; b[7] = b1.w;
#pragma unroll
            for (int i = 0; i < 8; i++)
#pragma unroll
                for (int j = 0; j < 8; j++) acc[i][j] += a[i] * b[j];
        }
        __syncthreads();
    }
#pragma unroll
    for (int i = 0; i < 8; i++) {
        int v = m0 + ty * 8 + i;
#pragma unroll
        for (int j = 0; j < 8; j++) {
            int w = n0 + tx * 8 + j;
            Bpk[((long)(512 + (v >> 1)) * 1024 + w) * 2 + (v & 1)] =
                __float2half(acc[i][j]);
        }
    }
}

// ---------------------------------------------------------------------------
// fused layer GEMM + gc tail. acc = mmA[M,2048] @ Bpk[2048,1024];
// hnew = (acc + mm0 + hold)*sc + sh. A frags via ldmatrix.x4.
// ---------------------------------------------------------------------------
__global__ __launch_bounds__(256) void k_gemm_gc(const __half* __restrict__ A,
                                                 const half2* __restrict__ Bpk,
                                                 float* __restrict__ hnew,
                                                 const float* __restrict__ hold,
                                                 const __half* __restrict__ mm0,
                                                 const float* __restrict__ bng,
                                                 const float* __restrict__ bnb,
                                                 int L0, int L1, int d) {
    __shared__ __half As[2][128][40];
    __shared__ half2  Bs[2][16][264];
    int tid = threadIdx.x;
    int m0 = blockIdx.y * 128;
    int n0 = blockIdx.x * 256;
    int w = tid >> 5, lane = tid & 31;
    int grp = lane >> 2, tg = lane & 3;
    int wm = (w & 1) * 64, wn = (w >> 1) * 64;
    int arow = lane & 15, akoff = (lane >> 4) * 8;
    unsigned asBase = (unsigned)__cvta_generic_to_shared(&As[0][0][0]);

    float acc[4][8][4];
#pragma unroll
    for (int mt = 0; mt < 4; mt++)
#pragma unroll
        for (int nt = 0; nt < 8; nt++)
#pragma unroll
            for (int c = 0; c < 4; c++) acc[mt][nt][c] = 0.f;

    const int nstage = 2048 / 32;
    {
#pragma unroll
        for (int i = 0; i < 2; i++) {
            int ch = tid + i * 256;
            int r = ch >> 2, p = (ch & 3) * 8;
            cp16(&As[0][r][p], A + (long)(m0 + r) * 2048 + p);
        }
#pragma unroll
        for (int i = 0; i < 4; i++) {
            int ch = tid + i * 256;
            int r = ch >> 6, c4 = (ch & 63) * 4;
            cp16(&Bs[0][r][c4], Bpk + (long)r * 1024 + n0 + c4);
        }
        asm volatile("cp.async.commit_group;\n");
    }

    for (int s = 0; s < nstage; s++) {
        int buf = s & 1;
        if (s + 1 < nstage) {
            int nb = buf ^ 1;
            int k0 = (s + 1) * 32;
#pragma unroll
            for (int i = 0; i < 2; i++) {
                int ch = tid + i * 256;
                int r = ch >> 2, p = (ch & 3) * 8;
                cp16(&As[nb][r][p], A + (long)(m0 + r) * 2048 + k0 + p);
            }
#pragma unroll
            for (int i = 0; i < 4; i++) {
                int ch = tid + i * 256;
                int r = ch >> 6, c4 = (ch & 63) * 4;
                cp16(&Bs[nb][r][c4], Bpk + (long)(k0 / 2 + r) * 1024 + n0 + c4);
            }
            asm volatile("cp.async.commit_group;\n");
            asm volatile("cp.async.wait_group 1;\n");
        } else {
            asm volatile("cp.async.wait_group 0;\n");
        }
        __syncthreads();

#pragma unroll
        for (int s2 = 0; s2 < 2; s2++) {
            unsigned a[4][4];
#pragma unroll
            for (int mt = 0; mt < 4; mt++) {
                unsigned addr = asBase +
                    (unsigned)(((buf << 7) + wm + mt * 16 + arow) * 40 +
                               s2 * 16 + akoff) * 2;
                asm volatile(
                    "ldmatrix.sync.aligned.m8n8.x4.shared.b16 {%0,%1,%2,%3}, [%4];\n"
                    : "=r"(a[mt][0]), "=r"(a[mt][1]), "=r"(a[mt][2]), "=r"(a[mt][3])
                    : "r"(addr));
            }
            unsigned b[8][2];
#pragma unroll
            for (int nt = 0; nt < 8; nt++) {
                int cb = wn + nt * 8 + grp;
                b[nt][0] = *(const unsigned*)&Bs[buf][s2 * 8 + tg][cb];
                b[nt][1] = *(const unsigned*)&Bs[buf][s2 * 8 + tg + 4][cb];
            }
#pragma unroll
            for (int mt = 0; mt < 4; mt++)
#pragma unroll
                for (int nt = 0; nt < 8; nt++) {
                    asm volatile(
                        "mma.sync.aligned.m16n8k16.row.col.f32.f16.f16.f32 "
                        "{%0,%1,%2,%3}, {%4,%5,%6,%7}, {%8,%9}, {%0,%1,%2,%3};\n"
                        : "+f"(acc[mt][nt][0]), "+f"(acc[mt][nt][1]),
                          "+f"(acc[mt][nt][2]), "+f"(acc[mt][nt][3])
                        : "r"(a[mt][0]), "r"(a[mt][1]), "r"(a[mt][2]), "r"(a[mt][3]),
                          "r"(b[nt][0]), "r"(b[nt][1]));
                }
        }
        __syncthreads();
    }

    const float rs = rsqrtf(1.f + 1e-5f);
#pragma unroll
    for (int mt = 0; mt < 4; mt++) {
        int row0 = m0 + wm + mt * 16 + grp;
        int row1 = row0 + 8;
        int blx = row0 >> 5;
        int b = blx / L1, l = blx - b * L1;
        long hbase = (long)(b * L0 + l + d) * 32;
        int co0 = row0 & 31, co1 = row1 & 31;
        float sc0 = bng[co0] * rs, sh0 = bnb[co0];
        float sc1 = bng[co1] * rs, sh1 = bnb[co1];
#pragma unroll
        for (int nt = 0; nt < 8; nt++) {
            int col = n0 + wn + nt * 8 + tg * 2;
            half2 q0 = *(const half2*)&mm0[(long)row0 * 1024 + col];
            half2 q1 = *(const half2*)&mm0[(long)row1 * 1024 + col];
            float2 r0 = *(const float2*)&hold[(hbase + co0) * 1024 + col];
            float2 r1 = *(const float2*)&hold[(hbase + co1) * 1024 + col];
            float2 o0, o1;
            o0.x = (acc[mt][nt][0] + __half2float(q0.x) + r0.x) * sc0 + sh0;
            o0.y = (acc[mt][nt][1] + __half2float(q0.y) + r0.y) * sc0 + sh0;
            o1.x = (acc[mt][nt][2] + __half2float(q1.x) + r1.x) * sc1 + sh1;
            o1.y = (acc[mt][nt][3] + __half2float(q1.y) + r1.y) * sc1 + sh1;
            *(float2*)&hnew[(long)row0 * 1024 + col] = o0;
            *(float2*)&hnew[(long)row1 * 1024 + col] = o1;
        }
    }
}

// ---------------------------------------------------------------------------
// generic fp16 GEMM (skip/end1), ldmatrix A. flags bit1: +bias relu.
// bit2: C k-packed half. bit3: C plain half. else fp32.
// ---------------------------------------------------------------------------
__global__ __launch_bounds__(256) void k_gemm_f16(const __half* __restrict__ A,
                                                  const half2* __restrict__ Bpk,
                                                  void* __restrict__ Cv,
                                                  int K, int lda, long ldb2, long ldc,
                                                  const float* __restrict__ bias,
                                                  int flags) {
    __shared__ __half As[2][128][40];
    __shared__ half2  Bs[2][16][264];
    int tid = threadIdx.x;
    int m0 = blockIdx.y * 128;
    long n0 = (long)blockIdx.x * 256;
    int w = tid >> 5, lane = tid & 31;
    int grp = lane >> 2, tg = lane & 3;
    int wm = (w & 1) * 64, wn = (w >> 1) * 64;
    int arow = lane & 15, akoff = (lane >> 4) * 8;
    unsigned asBase = (unsigned)__cvta_generic_to_shared(&As[0][0][0]);

    float acc[4][8][4];
#pragma unroll
    for (int mt = 0; mt < 4; mt++)
#pragma unroll
        for (int nt = 0; nt < 8; nt++)
#pragma unroll
            for (int c = 0; c < 4; c++) acc[mt][nt][c] = 0.f;

    int nstage = K / 32;
    {
#pragma unroll
        for (int i = 0; i < 2; i++) {
            int ch = tid + i * 256;
            int r = ch >> 2, p = (ch & 3) * 8;
            cp16(&As[0][r][p], A + (long)(m0 + r) * lda + p);
        }
#pragma unroll
        for (int i = 0; i < 4; i++) {
            int ch = tid + i * 256;
            int r = ch >> 6, c4 = (ch & 63) * 4;
            cp16(&Bs[0][r][c4], Bpk + (long)r * ldb2 + n0 + c4);
        }
        asm volatile("cp.async.commit_group;\n");
    }

    for (int s = 0; s < nstage; s++) {
        int buf = s & 1;
        if (s + 1 < nstage) {
            int nb = buf ^ 1;
            int k0 = (s + 1) * 32;
#pragma unroll
            for (int i = 0; i < 2; i++) {
                int ch = tid + i * 256;
                int r = ch >> 2, p = (ch & 3) * 8;
                cp16(&As[nb][r][p], A + (long)(m0 + r) * lda + k0 + p);
            }
#pragma unroll
            for (int i = 0; i < 4; i++) {
                int ch = tid + i * 256;
                int r = ch >> 6, c4 = (ch & 63) * 4;
                cp16(&Bs[nb][r][c4], Bpk + (long)(k0 / 2 + r) * ldb2 + n0 + c4);
            }
            asm volatile("cp.async.commit_group;\n");
            asm volatile("cp.async.wait_group 1;\n");
        } else {
            asm volatile("cp.async.wait_group 0;\n");
        }
        __syncthreads();

#pragma unroll
        for (int s2 = 0; s2 < 2; s2++) {
            unsigned a[4][4];
#pragma unroll
            for (int mt = 0; mt < 4; mt++) {
                unsigned addr = asBase +
                    (unsigned)(((buf << 7) + wm + mt * 16 + arow) * 40 +
                               s2 * 16 + akoff) * 2;
                asm volatile(
                    "ldmatrix.sync.aligned.m8n8.x4.shared.b16 {%0,%1,%2,%3}, [%4];\n"
                    : "=r"(a[mt][0]), "=r"(a[mt][1]), "=r"(a[mt][2]), "=r"(a[mt][3])
                    : "r"(addr));
            }
            unsigned b[8][2];
#pragma unroll
            for (int nt = 0; nt < 8; nt++) {
                int cb = wn + nt * 8 + grp;
                b[nt][0] = *(const unsigned*)&Bs[buf][s2 * 8 + tg][cb];
                b[nt][1] = *(const unsigned*)&Bs[buf][s2 * 8 + tg + 4][cb];
            }
#pragma unroll
            for (int mt = 0; mt < 4; mt++)
#pragma unroll
                for (int nt = 0; nt < 8; nt++) {
                    asm volatile(
                        "mma.sync.aligned.m16n8k16.row.col.f32.f16.f16.f32 "
                        "{%0,%1,%2,%3}, {%4,%5,%6,%7}, {%8,%9}, {%0,%1,%2,%3};\n"
                        : "+f"(acc[mt][nt][0]), "+f"(acc[mt][nt][1]),
                          "+f"(acc[mt][nt][2]), "+f"(acc[mt][nt][3])
                        : "r"(a[mt][0]), "r"(a[mt][1]), "r"(a[mt][2]), "r"(a[mt][3]),
                          "r"(b[nt][0]), "r"(b[nt][1]));
                }
        }
        __syncthreads();
    }

    float* Cf = (float*)Cv;
    __half* Ch = (__half*)Cv;
#pragma unroll
    for (int mt = 0; mt < 4; mt++) {
        int row0 = m0 + wm + mt * 16 + grp;
        int row1 = row0 + 8;
        float b0 = 0.f, b1 = 0.f;
        if (flags & 2) { b0 = bias[row0]; b1 = bias[row1]; }
#pragma unroll
        for (int nt = 0; nt < 8; nt++) {
            long col = n0 + wn + nt * 8 + tg * 2;
            float v00 = acc[mt][nt][0], v01 = acc[mt][nt][1];
            float v10 = acc[mt][nt][2], v11 = acc[mt][nt][3];
            if (flags & 2) {
                v00 = fmaxf(v00 + b0, 0.f); v01 = fmaxf(v01 + b0, 0.f);
                v10 = fmaxf(v10 + b1, 0.f); v11 = fmaxf(v11 + b1, 0.f);
            }
            if (flags & 4) {
                long p0 = ((long)(row0 >> 1) * ldc + col) * 2 + (row0 & 1);
                long p1 = ((long)(row1 >> 1) * ldc + col) * 2 + (row1 & 1);
                Ch[p0] = __float2half(v00); Ch[p0 + 2] = __float2half(v01);
                Ch[p1] = __float2half(v10); Ch[p1 + 2] = __float2half(v11);
            } else if (flags & 8) {
                *(half2*)(Ch + (long)row0 * ldc + col) = __floats2half2_rn(v00, v01);
                *(half2*)(Ch + (long)row1 * ldc + col) = __floats2half2_rn(v10, v11);
            } else {
                *(float2*)(Cf + (long)row0 * ldc + col) = make_float2(v00, v01);
                *(float2*)(Cf + (long)row1 * ldc + col) = make_float2(v10, v11);
            }
        }
    }
}

// ---------------------------------------------------------------------------
__global__ __launch_bounds__(256) void k_prep(const float* __restrict__ skw,
                                              const float* __restrict__ skb,
                                              __half* __restrict__ wcat,
                                              float* __restrict__ bsum) {
    int co = blockIdx.x, k = threadIdx.x;
    int i = k >> 5, ci = k & 31;
    wcat[co * 256 + k] = __float2half(skw[((long)i * 256 + co) * 32 + ci]);
    if (k == 0) {
        float s = 0.f;
#pragma unroll
        for (int j = 0; j < 8; j++) s += skb[j * 256 + co];
        bsum[co] = s;
    }
}
__global__ __launch_bounds__(256) void k_roundh(const float* __restrict__ w,
                                                __half* __restrict__ o) {
    int i = blockIdx.x * 256 + threadIdx.x;
    o[i] = __float2half(w[i]);
}

// ---------------------------------------------------------------------------
__global__ __launch_bounds__(256) void k_end2(const __half* __restrict__ e1,
                                              const float* __restrict__ w2,
                                              const float* __restrict__ b2,
                                              float* __restrict__ out) {
    __shared__ float s_w[12 * 512];
    int tid = threadIdx.x;
    for (int idx = tid; idx < 6144; idx += 256) s_w[idx] = w2[idx];
    __syncthreads();
    int col = blockIdx.x * 256 + tid;
    int b = col >> 10, n = col & 1023;
    float acc[12];
#pragma unroll
    for (int o = 0; o < 12; o++) acc[o] = b2[o];
    for (int c = 0; c < 512; c++) {
        float v = __half2float(e1[(long)c * 65536 + col]);
#pragma unroll
        for (int o = 0; o < 12; o++) acc[o] += s_w[o * 512 + c] * v;
    }
#pragma unroll
    for (int o = 0; o < 12; o++) out[((long)b * 12 + o) * 1024 + n] = acc[o];
}

// ---------------------------------------------------------------------------
extern "C" void kernel_launch(void* const* d_in, const int* in_sizes, int n_in,
                              void* d_out, int out_size) {
    const float* x        = (const float*)d_in[0];
    const float* start_w  = (const float*)d_in[1];
    const float* start_b  = (const float*)d_in[2];
    const float* nodevec1 = (const float*)d_in[3];
    const float* nodevec2 = (const float*)d_in[4];
    const float* filter_w = (const float*)d_in[5];
    const float* filter_b = (const float*)d_in[6];
    const float* gate_w   = (const float*)d_in[7];
    const float* gate_b   = (const float*)d_in[8];
    const float* skip_w   = (const float*)d_in[9];
    const float* skip_b   = (const float*)d_in[10];
    const float* gc_w     = (const float*)d_in[11];
    const float* gc_b     = (const float*)d_in[12];
    const float* bn_g     = (const float*)d_in[13];
    const float* bn_b     = (const float*)d_in[14];
    const float* end1_w   = (const float*)d_in[15];
    const float* end1_b   = (const float*)d_in[16];
    const float* end2_w   = (const float*)d_in[17];
    const float* end2_b   = (const float*)d_in[18];

    float *hA, *hB, *adpf, *bsk;
    __half *mmA, *mm0, *Bm, *msk, *skip, *e1, *w1r, *wsk;
    cudaGetSymbolAddress((void**)&hA, g_hA);
    cudaGetSymbolAddress((void**)&hB, g_hB);
    cudaGetSymbolAddress((void**)&mmA, g_mmA);
    cudaGetSymbolAddress((void**)&mm0, g_mm0);
    cudaGetSymbolAddress((void**)&adpf, g_adpf);
    cudaGetSymbolAddress((void**)&Bm, g_Bm);
    cudaGetSymbolAddress((void**)&msk, g_msk);
    cudaGetSymbolAddress((void**)&skip, g_skip);
    cudaGetSymbolAddress((void**)&e1, g_e1);
    cudaGetSymbolAddress((void**)&w1r, g_w1r);
    cudaGetSymbolAddress((void**)&wsk, g_wsk);
    cudaGetSymbolAddress((void**)&bsk, g_bsk);

    k_adp<<<1024, 256>>>(nodevec1, nodevec2, adpf, Bm);
    k_sgemm<<<dim3(8, 8), 256>>>(adpf, adpf, Bm);
    k_start<<<dim3(64 * 13, 4), 256>>>(x, start_w, start_b, hA);
    k_roundh<<<512, 256>>>(end1_w, w1r);
    k_prep<<<256, 256>>>(skip_w, skip_b, wsk, bsk);

    const int lens[9] = {13, 12, 10, 9, 7, 6, 4, 3, 1};
    const int dil[8]  = {1, 2, 1, 2, 1, 2, 1, 2};
    float* hcur = hA;
    float* hnext = hB;

    for (int i = 0; i < 8; i++) {
        int L0 = lens[i], L1 = lens[i + 1], d = dil[i];
        int doPre = (i < 7) ? 1 : 0;
        k_dconv<<<dim3(64 * L1, 16), 256>>>(hcur,
                                            filter_w + i * 2048, filter_b + i * 32,
                                            gate_w + i * 2048, gate_b + i * 32,
                                            gc_w + i * 32 * 96, gc_b + i * 32,
                                            mmA, mm0, msk, L0, L1, d, i, doPre);
        if (i < 7) {
            int M = 2048 * L1;
            k_gemm_gc<<<dim3(4, M / 128), 256>>>(
                mmA, (const half2*)Bm, hnext, hcur, mm0,
                bn_g + i * 32, bn_b + i * 32, L0, L1, d);
            float* t = hcur; hcur = hnext; hnext = t;
        }
    }

    k_gemm_f16<<<dim3(65536 / 256, 2), 256>>>(
        wsk, (const half2*)msk, skip, 256, 256, 65536, 65536, bsk, 2 | 4);
    k_gemm_f16<<<dim3(65536 / 256, 4), 256>>>(
        w1r, (const half2*)skip, e1, 256, 256, 65536, 65536, end1_b, 2 | 8);
    k_end2<<<256, 256>>>(e1, end2_w, end2_b, (float*)d_out);
}